// round 4
// baseline (speedup 1.0000x reference)
#include <cuda_runtime.h>
#include <stdint.h>

#define C_DIM   256
#define NGROUP  32
#define CPG     8
#define NET     7
#define NBATCH  8
#define GN_EPS  1e-5f
#define MAXN    100000
#define NPB     128      // nodes per block in gnstats

// ---------------- scratch (device globals; no allocation allowed) ----------------
__device__ float g_h  [(size_t)MAXN * C_DIM];          // 102.4 MB
__device__ float g_acc[(size_t)MAXN * C_DIM];          // 102.4 MB (conv1 output)
__device__ float g_Y  [(size_t)MAXN * NET * C_DIM];    // 716.8 MB (h @ W')
__device__ int   g_cnt[MAXN * NET];
__device__ float g_s1 [NBATCH * NGROUP];
__device__ float g_s2 [NBATCH * NGROUP];
__device__ float g_mean[NBATCH * NGROUP];
__device__ float g_istd[NBATCH * NGROUP];
__device__ float g_bcnt[NBATCH];

// ---------------- small utility kernels ----------------
__global__ void k_zero_cnt_stats(int n7) {
    int i = blockIdx.x * blockDim.x + threadIdx.x;
    if (i < n7) g_cnt[i] = 0;
    if (i < NBATCH * NGROUP) { g_s1[i] = 0.f; g_s2[i] = 0.f; }
    if (i < NBATCH) g_bcnt[i] = 0.f;
}

__global__ void k_zero_stats() {
    int i = threadIdx.x;            // 256 threads
    g_s1[i] = 0.f; g_s2[i] = 0.f;
}

__global__ void k_zero_acc(int n4) {
    int i = blockIdx.x * blockDim.x + threadIdx.x;
    if (i < n4) ((float4*)g_acc)[i] = make_float4(0.f, 0.f, 0.f, 0.f);
}

__global__ void k_bcount(const int* __restrict__ bid, int N) {
    __shared__ int sc[NBATCH];
    if (threadIdx.x < NBATCH) sc[threadIdx.x] = 0;
    __syncthreads();
    int i = blockIdx.x * blockDim.x + threadIdx.x;
    if (i < N) atomicAdd(&sc[bid[i]], 1);
    __syncthreads();
    if (threadIdx.x < NBATCH && sc[threadIdx.x] > 0)
        atomicAdd(&g_bcnt[threadIdx.x], (float)sc[threadIdx.x]);
}

// ---------------- GN stats: one thread per channel column, NPB nodes per block ----------------
__global__ void k_gnstats(const float* __restrict__ src, const int* __restrict__ bid, int N) {
    __shared__ int sbid[NPB];
    int n0 = blockIdx.x * NPB;
    int nmax = min(N - n0, NPB);
    for (int i = threadIdx.x; i < nmax; i += blockDim.x) sbid[i] = bid[n0 + i];
    __syncthreads();

    int c = threadIdx.x;            // 256 threads = channels
    int g = c >> 3;                 // group (cpg = 8)
    float ls1 = 0.f, ls2 = 0.f;
    int cur = sbid[0];
    for (int i = 0; i < nmax; ++i) {
        int b = sbid[i];
        if (b != cur) {             // batch_id is sorted; flush on boundary
            atomicAdd(&g_s1[cur * NGROUP + g], ls1);
            atomicAdd(&g_s2[cur * NGROUP + g], ls2);
            ls1 = 0.f; ls2 = 0.f; cur = b;
        }
        float v = src[(size_t)(n0 + i) * C_DIM + c];
        ls1 += v; ls2 += v * v;
    }
    atomicAdd(&g_s1[cur * NGROUP + g], ls1);
    atomicAdd(&g_s2[cur * NGROUP + g], ls2);
}

__global__ void k_gnfinal() {
    int i = threadIdx.x;            // 256 = NBATCH * NGROUP
    int b = i >> 5;
    float n  = g_bcnt[b] * (float)CPG;        // count * cpg
    float ic = 1.0f / (n + GN_EPS);           // matches reference inv_count
    float s1 = g_s1[i], s2 = g_s2[i];
    float m  = s1 * ic;
    float var = ic * (s2 - 2.f * m * s1 + m * m * n);   // exact sum of (x-m)^2 * ic
    g_mean[i] = m;
    g_istd[i] = rsqrtf(var + GN_EPS);
}

__global__ void k_gn_silu(const float* __restrict__ src, float* __restrict__ dst,
                          const float* __restrict__ w, const float* __restrict__ bb,
                          const int* __restrict__ bid, int N) {
    int i = blockIdx.x * blockDim.x + threadIdx.x;    // float4 index
    int total = N * (C_DIM / 4);
    if (i >= total) return;
    int n  = i >> 6;
    int c4 = (i & 63) << 2;                            // base channel, multiple of 4
    int b  = bid[n];
    int s  = b * NGROUP + (c4 >> 3);
    float m  = g_mean[s], is = g_istd[s];
    float4 xv = ((const float4*)src)[i];
    float4 wv = ((const float4*)w)[c4 >> 2];
    float4 bv = ((const float4*)bb)[c4 >> 2];
    float4 o; float v;
    v = (xv.x - m) * is * wv.x + bv.x; o.x = v / (1.f + expf(-v));
    v = (xv.y - m) * is * wv.y + bv.y; o.y = v / (1.f + expf(-v));
    v = (xv.z - m) * is * wv.z + bv.z; o.z = v / (1.f + expf(-v));
    v = (xv.w - m) * is * wv.w + bv.w; o.w = v / (1.f + expf(-v));
    ((float4*)dst)[i] = o;
}

__global__ void k_ecount(const int* __restrict__ erow, const int* __restrict__ et, int E) {
    int e = blockIdx.x * blockDim.x + threadIdx.x;
    if (e < E) atomicAdd(&g_cnt[erow[e] * NET + et[e]], 1);
}

// ---------------- tf32 tensor-core GEMM: Y[N,1792] = A[N,256] @ B ----------------
// B[k][t*256+o] = W[(t*256+k)*256 + o]; each 128-wide N tile lies in one t-block.
#define BM 128
#define BN 128
#define BK 32

__device__ __forceinline__ float to_tf32(float x) {
    float r; asm("cvt.rna.tf32.f32 %0, %1;" : "=f"(r) : "f"(x)); return r;
}

__device__ __forceinline__ void mma_tf32(float* d, const uint32_t* a, uint32_t b0, uint32_t b1) {
    asm volatile("mma.sync.aligned.m16n8k8.row.col.f32.tf32.tf32.f32 "
        "{%0,%1,%2,%3}, {%4,%5,%6,%7}, {%8,%9}, {%0,%1,%2,%3};\n"
        : "+f"(d[0]), "+f"(d[1]), "+f"(d[2]), "+f"(d[3])
        : "r"(a[0]), "r"(a[1]), "r"(a[2]), "r"(a[3]), "r"(b0), "r"(b1));
}

__global__ __launch_bounds__(256, 2)
void k_gemm(const float* __restrict__ A, const float* __restrict__ W,
            float* __restrict__ Y, int N) {
    __shared__ float As[BM][BK + 4];     // m-major: conflict-free a-frag loads
    __shared__ float Bs[BK][BN + 8];     // k-major: conflict-free b-frag loads

    int n0 = blockIdx.x * BN;            // 0..1791 in steps of 128
    int m0 = blockIdx.y * BM;
    int t  = n0 >> 8;                    // edge-type block
    int o0 = n0 & 255;
    const float* Bg = W + (size_t)(t * 256) * C_DIM + o0;   // Bg[k*256 + n]

    int tid  = threadIdx.x;
    int warp = tid >> 5, lane = tid & 31;
    int wm = warp >> 1, wn = warp & 1;          // 4x2 warps, warp tile 32x64
    int mBase = wm * 32, nBase = wn * 64;
    int grp = lane >> 2, tig = lane & 3;

    int arow = tid >> 3;                 // 0..31
    int aq   = tid & 7;                  // 0..7 (float4 within 32-float row)

    float acc[2][8][4];
    #pragma unroll
    for (int i = 0; i < 2; ++i)
        #pragma unroll
        for (int j = 0; j < 8; ++j)
            #pragma unroll
            for (int q = 0; q < 4; ++q) acc[i][j][q] = 0.f;

    for (int kb = 0; kb < C_DIM; kb += BK) {
        float4 aReg[4], bReg[4];
        #pragma unroll
        for (int p = 0; p < 4; ++p) {
            int r = arow + p * 32;
            if (m0 + r < N)
                aReg[p] = *(const float4*)(A + (size_t)(m0 + r) * C_DIM + kb + aq * 4);
            else
                aReg[p] = make_float4(0.f, 0.f, 0.f, 0.f);
        }
        #pragma unroll
        for (int p = 0; p < 4; ++p) {
            int q = aq + p * 8;          // 0..31 float4s along n
            bReg[p] = *(const float4*)(Bg + (size_t)(kb + arow) * C_DIM + q * 4);
        }
        __syncthreads();
        #pragma unroll
        for (int p = 0; p < 4; ++p) {
            int r = arow + p * 32;
            As[r][aq * 4 + 0] = to_tf32(aReg[p].x);
            As[r][aq * 4 + 1] = to_tf32(aReg[p].y);
            As[r][aq * 4 + 2] = to_tf32(aReg[p].z);
            As[r][aq * 4 + 3] = to_tf32(aReg[p].w);
        }
        #pragma unroll
        for (int p = 0; p < 4; ++p) {
            int q = aq + p * 8;
            Bs[arow][q * 4 + 0] = to_tf32(bReg[p].x);
            Bs[arow][q * 4 + 1] = to_tf32(bReg[p].y);
            Bs[arow][q * 4 + 2] = to_tf32(bReg[p].z);
            Bs[arow][q * 4 + 3] = to_tf32(bReg[p].w);
        }
        __syncthreads();

        #pragma unroll
        for (int ks = 0; ks < 4; ++ks) {
            int k = ks * 8;
            uint32_t a[2][4];
            #pragma unroll
            for (int im = 0; im < 2; ++im) {
                int r = mBase + im * 16 + grp;
                a[im][0] = __float_as_uint(As[r    ][k + tig    ]);
                a[im][1] = __float_as_uint(As[r + 8][k + tig    ]);
                a[im][2] = __float_as_uint(As[r    ][k + tig + 4]);
                a[im][3] = __float_as_uint(As[r + 8][k + tig + 4]);
            }
            #pragma unroll
            for (int in = 0; in < 8; ++in) {
                int nn = nBase + in * 8 + grp;
                uint32_t b0 = __float_as_uint(Bs[k + tig    ][nn]);
                uint32_t b1 = __float_as_uint(Bs[k + tig + 4][nn]);
                mma_tf32(acc[0][in], a[0], b0, b1);
                mma_tf32(acc[1][in], a[1], b0, b1);
            }
        }
        __syncthreads();
    }

    // epilogue
    #pragma unroll
    for (int im = 0; im < 2; ++im) {
        int r0 = m0 + mBase + im * 16 + grp;
        #pragma unroll
        for (int in = 0; in < 8; ++in) {
            int cc = n0 + nBase + in * 8 + tig * 2;
            if (r0 < N)
                *(float2*)(Y + (size_t)r0 * (NET * C_DIM) + cc) =
                    make_float2(acc[im][in][0], acc[im][in][1]);
            if (r0 + 8 < N)
                *(float2*)(Y + (size_t)(r0 + 8) * (NET * C_DIM) + cc) =
                    make_float2(acc[im][in][2], acc[im][in][3]);
        }
    }
}

// ---------------- edge scatter: out[row] += Y[col, t*256:+256] / max(cnt[row,t],1) ----------------
__global__ void k_scatter(const float* __restrict__ Y, float* __restrict__ out,
                          const int* __restrict__ erow, const int* __restrict__ ecol,
                          const int* __restrict__ et, int E) {
    int gid = blockIdx.x * blockDim.x + threadIdx.x;
    int e = gid >> 5;
    int lane = gid & 31;
    if (e >= E) return;
    int r = erow[e], c = ecol[e], t = et[e];
    int cn = g_cnt[r * NET + t];
    float inv = 1.0f / (float)(cn > 0 ? cn : 1);
    const float4* src = (const float4*)(Y + (size_t)c * (NET * C_DIM) + t * C_DIM);
    float* dst = out + (size_t)r * C_DIM;
    #pragma unroll
    for (int i = 0; i < 2; ++i) {
        float4 v = src[lane + 32 * i];
        int ch = (lane + 32 * i) * 4;
        atomicAdd(dst + ch + 0, v.x * inv);
        atomicAdd(dst + ch + 1, v.y * inv);
        atomicAdd(dst + ch + 2, v.z * inv);
        atomicAdd(dst + ch + 3, v.w * inv);
    }
}

// ---------------- launch ----------------
extern "C" void kernel_launch(void* const* d_in, const int* in_sizes, int n_in,
                              void* d_out, int out_size) {
    const float* x    = (const float*)d_in[0];
    const float* gn1w = (const float*)d_in[1];
    const float* gn1b = (const float*)d_in[2];
    const float* w1   = (const float*)d_in[3];
    const float* gn2w = (const float*)d_in[4];
    const float* gn2b = (const float*)d_in[5];
    const float* w2   = (const float*)d_in[6];
    const int*   eidx = (const int*)d_in[7];
    const int*   et   = (const int*)d_in[8];
    const int*   bid  = (const int*)d_in[9];

    int N = in_sizes[0] / C_DIM;
    int E = in_sizes[8];
    const int* erow = eidx;
    const int* ecol = eidx + E;

    float *p_h, *p_acc, *p_Y;
    cudaGetSymbolAddress((void**)&p_h,   g_h);
    cudaGetSymbolAddress((void**)&p_acc, g_acc);
    cudaGetSymbolAddress((void**)&p_Y,   g_Y);

    int n7 = N * NET;
    int t4 = N * (C_DIM / 4);
    int gnBlocks = (N + NPB - 1) / NPB;
    dim3 gemmGrid(NET * C_DIM / BN, (N + BM - 1) / BM);
    unsigned scatBlocks = (unsigned)(((long long)E * 32 + 255) / 256);

    // --- stage 0: init ---
    k_zero_cnt_stats<<<(n7 + 255) / 256, 256>>>(n7);
    k_bcount<<<(N + 255) / 256, 256>>>(bid, N);

    // --- GN1 + silu ---
    k_gnstats<<<gnBlocks, 256>>>(x, bid, N);
    k_gnfinal<<<1, 256>>>();
    k_gn_silu<<<(t4 + 255) / 256, 256>>>(x, p_h, gn1w, gn1b, bid, N);

    // --- conv1: GEMM then scatter-mean ---
    k_ecount<<<(E + 255) / 256, 256>>>(erow, et, E);
    k_gemm<<<gemmGrid, 256>>>(p_h, w1, p_Y, N);
    k_zero_acc<<<(t4 + 255) / 256, 256>>>(t4);
    k_scatter<<<scatBlocks, 256>>>(p_Y, p_acc, erow, ecol, et, E);

    // --- GN2 + silu ---
    k_zero_stats<<<1, 256>>>();
    k_gnstats<<<gnBlocks, 256>>>(p_acc, bid, N);
    k_gnfinal<<<1, 256>>>();
    k_gn_silu<<<(t4 + 255) / 256, 256>>>(p_acc, p_h, gn2w, gn2b, bid, N);

    // --- conv2 + residual ---
    k_gemm<<<gemmGrid, 256>>>(p_h, w2, p_Y, N);
    cudaMemcpyAsync(d_out, x, (size_t)N * C_DIM * sizeof(float),
                    cudaMemcpyDeviceToDevice);
    k_scatter<<<scatBlocks, 256>>>(p_Y, (float*)d_out, erow, ecol, et, E);
}

// round 5
// speedup vs baseline: 1.4008x; 1.4008x over previous
#include <cuda_runtime.h>
#include <stdint.h>

#define C_DIM   256
#define NGROUP  32
#define CPG     8
#define NET     7
#define NBATCH  8
#define GN_EPS  1e-5f
#define MAXN    100000
#define MAXE    1048576
#define NPB     128      // nodes per block in gnstats
#define SCAN_B  2048     // elements per scan block

// ---------------- scratch (device globals; no allocation allowed) ----------------
__device__ float g_h  [(size_t)MAXN * C_DIM];          // 102.4 MB
__device__ float g_acc[(size_t)MAXN * C_DIM];          // 102.4 MB (conv1 output)
__device__ float g_Y  [(size_t)MAXN * NET * C_DIM];    // 716.8 MB (h @ W')
__device__ int   g_cnt[MAXN * NET];
__device__ int   g_rowcnt[MAXN];
__device__ int   g_offs[MAXN];
__device__ int   g_cur[MAXN];
__device__ int   g_blksum[64];
__device__ int   g_eperm[MAXE];
__device__ float g_s1 [NBATCH * NGROUP];
__device__ float g_s2 [NBATCH * NGROUP];
__device__ float g_mean[NBATCH * NGROUP];
__device__ float g_istd[NBATCH * NGROUP];
__device__ float g_bcnt[NBATCH];

// ---------------- init ----------------
__global__ void k_init(int N, int n7) {
    int i = blockIdx.x * blockDim.x + threadIdx.x;
    if (i < n7) g_cnt[i] = 0;
    if (i < N) { g_rowcnt[i] = 0; g_cur[i] = 0; }
    if (i < NBATCH * NGROUP) { g_s1[i] = 0.f; g_s2[i] = 0.f; }
    if (i < NBATCH) g_bcnt[i] = 0.f;
}

__global__ void k_zero_stats() {
    int i = threadIdx.x;
    g_s1[i] = 0.f; g_s2[i] = 0.f;
}

__global__ void k_bcount(const int* __restrict__ bid, int N) {
    __shared__ int sc[NBATCH];
    if (threadIdx.x < NBATCH) sc[threadIdx.x] = 0;
    __syncthreads();
    int i = blockIdx.x * blockDim.x + threadIdx.x;
    if (i < N) atomicAdd(&sc[bid[i]], 1);
    __syncthreads();
    if (threadIdx.x < NBATCH && sc[threadIdx.x] > 0)
        atomicAdd(&g_bcnt[threadIdx.x], (float)sc[threadIdx.x]);
}

// ---------------- GN stats ----------------
__global__ void k_gnstats(const float* __restrict__ src, const int* __restrict__ bid, int N) {
    __shared__ int sbid[NPB];
    int n0 = blockIdx.x * NPB;
    int nmax = min(N - n0, NPB);
    for (int i = threadIdx.x; i < nmax; i += blockDim.x) sbid[i] = bid[n0 + i];
    __syncthreads();

    int c = threadIdx.x;            // 256 threads = channels
    int g = c >> 3;
    float ls1 = 0.f, ls2 = 0.f;
    int cur = sbid[0];
    for (int i = 0; i < nmax; ++i) {
        int b = sbid[i];
        if (b != cur) {
            atomicAdd(&g_s1[cur * NGROUP + g], ls1);
            atomicAdd(&g_s2[cur * NGROUP + g], ls2);
            ls1 = 0.f; ls2 = 0.f; cur = b;
        }
        float v = src[(size_t)(n0 + i) * C_DIM + c];
        ls1 += v; ls2 += v * v;
    }
    atomicAdd(&g_s1[cur * NGROUP + g], ls1);
    atomicAdd(&g_s2[cur * NGROUP + g], ls2);
}

__global__ void k_gnfinal() {
    int i = threadIdx.x;            // 256 = NBATCH * NGROUP
    int b = i >> 5;
    float n  = g_bcnt[b] * (float)CPG;
    float ic = 1.0f / (n + GN_EPS);
    float s1 = g_s1[i], s2 = g_s2[i];
    float m  = s1 * ic;
    float var = ic * (s2 - 2.f * m * s1 + m * m * n);
    g_mean[i] = m;
    g_istd[i] = rsqrtf(var + GN_EPS);
}

__global__ void k_gn_silu(const float* __restrict__ src, float* __restrict__ dst,
                          const float* __restrict__ w, const float* __restrict__ bb,
                          const int* __restrict__ bid, int N) {
    int i = blockIdx.x * blockDim.x + threadIdx.x;    // float4 index
    int total = N * (C_DIM / 4);
    if (i >= total) return;
    int n  = i >> 6;
    int c4 = (i & 63) << 2;
    int b  = bid[n];
    int s  = b * NGROUP + (c4 >> 3);
    float m  = g_mean[s], is = g_istd[s];
    float4 xv = ((const float4*)src)[i];
    float4 wv = ((const float4*)w)[c4 >> 2];
    float4 bv = ((const float4*)bb)[c4 >> 2];
    float4 o; float v;
    v = (xv.x - m) * is * wv.x + bv.x; o.x = v / (1.f + expf(-v));
    v = (xv.y - m) * is * wv.y + bv.y; o.y = v / (1.f + expf(-v));
    v = (xv.z - m) * is * wv.z + bv.z; o.z = v / (1.f + expf(-v));
    v = (xv.w - m) * is * wv.w + bv.w; o.w = v / (1.f + expf(-v));
    ((float4*)dst)[i] = o;
}

// ---------------- CSR build ----------------
__global__ void k_ecount2(const int* __restrict__ erow, const int* __restrict__ et, int E) {
    int e = blockIdx.x * blockDim.x + threadIdx.x;
    if (e < E) {
        int r = erow[e];
        atomicAdd(&g_cnt[r * NET + et[e]], 1);
        atomicAdd(&g_rowcnt[r], 1);
    }
}

__global__ void k_scan1(int N) {
    __shared__ int sh[256];
    int base = blockIdx.x * SCAN_B;
    int tid = threadIdx.x;
    int vals[8];
    int s = 0;
    #pragma unroll
    for (int j = 0; j < 8; ++j) {
        int idx = base + tid * 8 + j;
        int v = (idx < N) ? g_rowcnt[idx] : 0;
        vals[j] = s;            // exclusive within thread chunk
        s += v;
    }
    sh[tid] = s;
    __syncthreads();
    for (int off = 1; off < 256; off <<= 1) {
        int t = (tid >= off) ? sh[tid - off] : 0;
        __syncthreads();
        sh[tid] += t;
        __syncthreads();
    }
    int tb = tid ? sh[tid - 1] : 0;
    #pragma unroll
    for (int j = 0; j < 8; ++j) {
        int idx = base + tid * 8 + j;
        if (idx < N) g_offs[idx] = tb + vals[j];
    }
    if (tid == 255) g_blksum[blockIdx.x] = sh[255];
}

__global__ void k_scan2(int nb) {
    __shared__ int sh[64];
    int t = threadIdx.x;
    sh[t] = (t < nb) ? g_blksum[t] : 0;
    __syncthreads();
    for (int off = 1; off < 64; off <<= 1) {
        int v = (t >= off) ? sh[t - off] : 0;
        __syncthreads();
        sh[t] += v;
        __syncthreads();
    }
    if (t < nb) g_blksum[t] = t ? sh[t - 1] : 0;
}

__global__ void k_scan3(int N) {
    int i = blockIdx.x * blockDim.x + threadIdx.x;
    if (i < N) g_offs[i] += g_blksum[i / SCAN_B];
}

__global__ void k_escatter(const int* __restrict__ erow, const int* __restrict__ ecol,
                           const int* __restrict__ et, int E) {
    int e = blockIdx.x * blockDim.x + threadIdx.x;
    if (e >= E) return;
    int r = erow[e];
    int pos = g_offs[r] + atomicAdd(&g_cur[r], 1);
    g_eperm[pos] = (ecol[e] << 3) | et[e];
}

// ---------------- tf32 tensor-core GEMM, double-buffered ----------------
#define BM 128
#define BN 128
#define BK 32
#define AS_LD 36
#define BS_LD 136
#define AS_SZ (BM * AS_LD)      // 4608 floats
#define BS_SZ (BK * BS_LD)      // 4352 floats
#define GEMM_SMEM ((2 * AS_SZ + 2 * BS_SZ) * 4)   // 71680 bytes

__device__ __forceinline__ float to_tf32(float x) {
    float r; asm("cvt.rna.tf32.f32 %0, %1;" : "=f"(r) : "f"(x)); return r;
}

__device__ __forceinline__ void mma_tf32(float* d, const uint32_t* a, uint32_t b0, uint32_t b1) {
    asm volatile("mma.sync.aligned.m16n8k8.row.col.f32.tf32.tf32.f32 "
        "{%0,%1,%2,%3}, {%4,%5,%6,%7}, {%8,%9}, {%0,%1,%2,%3};\n"
        : "+f"(d[0]), "+f"(d[1]), "+f"(d[2]), "+f"(d[3])
        : "r"(a[0]), "r"(a[1]), "r"(a[2]), "r"(a[3]), "r"(b0), "r"(b1));
}

__global__ __launch_bounds__(256, 2)
void k_gemm(const float* __restrict__ A, const float* __restrict__ W,
            float* __restrict__ Y, int N) {
    extern __shared__ float sm[];
    float* AsB = sm;                  // 2 buffers of [BM][AS_LD]
    float* BsB = sm + 2 * AS_SZ;      // 2 buffers of [BK][BS_LD]

    int n0 = blockIdx.x * BN;
    int m0 = blockIdx.y * BM;
    int t  = n0 >> 8;
    int o0 = n0 & 255;
    const float* Bg = W + (size_t)(t * 256) * C_DIM + o0;

    int tid  = threadIdx.x;
    int warp = tid >> 5, lane = tid & 31;
    int wm = warp >> 1, wn = warp & 1;
    int mBase = wm * 32, nBase = wn * 64;
    int grp = lane >> 2, tig = lane & 3;
    int arow = tid >> 3;
    int aq   = tid & 7;

    float4 aReg[4], bReg[4];
    float acc[2][8][4];
    #pragma unroll
    for (int i = 0; i < 2; ++i)
        #pragma unroll
        for (int j = 0; j < 8; ++j)
            #pragma unroll
            for (int q = 0; q < 4; ++q) acc[i][j][q] = 0.f;

    auto loadRegs = [&](int kb) {
        #pragma unroll
        for (int p = 0; p < 4; ++p) {
            int r = arow + p * 32;
            if (m0 + r < N)
                aReg[p] = *(const float4*)(A + (size_t)(m0 + r) * C_DIM + kb + aq * 4);
            else
                aReg[p] = make_float4(0.f, 0.f, 0.f, 0.f);
        }
        #pragma unroll
        for (int p = 0; p < 4; ++p) {
            int q = aq + p * 8;
            bReg[p] = *(const float4*)(Bg + (size_t)(kb + arow) * C_DIM + q * 4);
        }
    };

    auto storeSmem = [&](int buf) {
        float* Ab = AsB + buf * AS_SZ;
        float* Bb = BsB + buf * BS_SZ;
        #pragma unroll
        for (int p = 0; p < 4; ++p) {
            int r = arow + p * 32;
            Ab[r * AS_LD + aq * 4 + 0] = to_tf32(aReg[p].x);
            Ab[r * AS_LD + aq * 4 + 1] = to_tf32(aReg[p].y);
            Ab[r * AS_LD + aq * 4 + 2] = to_tf32(aReg[p].z);
            Ab[r * AS_LD + aq * 4 + 3] = to_tf32(aReg[p].w);
        }
        #pragma unroll
        for (int p = 0; p < 4; ++p) {
            int q = aq + p * 8;
            Bb[arow * BS_LD + q * 4 + 0] = to_tf32(bReg[p].x);
            Bb[arow * BS_LD + q * 4 + 1] = to_tf32(bReg[p].y);
            Bb[arow * BS_LD + q * 4 + 2] = to_tf32(bReg[p].z);
            Bb[arow * BS_LD + q * 4 + 3] = to_tf32(bReg[p].w);
        }
    };

    auto compute = [&](int buf) {
        float* Ab = AsB + buf * AS_SZ;
        float* Bb = BsB + buf * BS_SZ;
        #pragma unroll
        for (int ks = 0; ks < 4; ++ks) {
            int k = ks * 8;
            uint32_t a[2][4];
            #pragma unroll
            for (int im = 0; im < 2; ++im) {
                int r = mBase + im * 16 + grp;
                a[im][0] = __float_as_uint(Ab[(r    ) * AS_LD + k + tig    ]);
                a[im][1] = __float_as_uint(Ab[(r + 8) * AS_LD + k + tig    ]);
                a[im][2] = __float_as_uint(Ab[(r    ) * AS_LD + k + tig + 4]);
                a[im][3] = __float_as_uint(Ab[(r + 8) * AS_LD + k + tig + 4]);
            }
            #pragma unroll
            for (int in = 0; in < 8; ++in) {
                int nn = nBase + in * 8 + grp;
                uint32_t b0 = __float_as_uint(Bb[(k + tig    ) * BS_LD + nn]);
                uint32_t b1 = __float_as_uint(Bb[(k + tig + 4) * BS_LD + nn]);
                mma_tf32(acc[0][in], a[0], b0, b1);
                mma_tf32(acc[1][in], a[1], b0, b1);
            }
        }
    };

    loadRegs(0);
    storeSmem(0);
    __syncthreads();
    #pragma unroll
    for (int it = 0; it < 8; ++it) {
        if (it < 7) loadRegs((it + 1) * BK);
        compute(it & 1);
        if (it < 7) {
            storeSmem((it + 1) & 1);   // other buffer: no pre-sync needed
            __syncthreads();
        }
    }

    #pragma unroll
    for (int im = 0; im < 2; ++im) {
        int r0 = m0 + mBase + im * 16 + grp;
        #pragma unroll
        for (int in = 0; in < 8; ++in) {
            int cc = n0 + nBase + in * 8 + tig * 2;
            if (r0 < N)
                *(float2*)(Y + (size_t)r0 * (NET * C_DIM) + cc) =
                    make_float2(acc[im][in][0], acc[im][in][1]);
            if (r0 + 8 < N)
                *(float2*)(Y + (size_t)(r0 + 8) * (NET * C_DIM) + cc) =
                    make_float2(acc[im][in][2], acc[im][in][3]);
        }
    }
}

// ---------------- gather: one warp per destination row, zero atomics ----------------
__global__ void k_gather(const float* __restrict__ Y, const float* __restrict__ resid,
                         float* __restrict__ out, int N, int addResid) {
    int w = (blockIdx.x * blockDim.x + threadIdx.x) >> 5;
    int lane = threadIdx.x & 31;
    if (w >= N) return;
    int beg = g_offs[w];
    int deg = g_rowcnt[w];
    const int* cntp = &g_cnt[w * NET];

    float4 a0 = make_float4(0.f, 0.f, 0.f, 0.f);
    float4 a1 = a0;

    int j = 0;
    for (; j + 2 <= deg; j += 2) {
        int p0 = g_eperm[beg + j];
        int p1 = g_eperm[beg + j + 1];
        int c0 = p0 >> 3, t0 = p0 & 7;
        int c1 = p1 >> 3, t1 = p1 & 7;
        float i0 = 1.f / (float)cntp[t0];
        float i1 = 1.f / (float)cntp[t1];
        const float4* s0 = (const float4*)(Y + (size_t)c0 * (NET * C_DIM) + t0 * C_DIM) + lane;
        const float4* s1 = (const float4*)(Y + (size_t)c1 * (NET * C_DIM) + t1 * C_DIM) + lane;
        float4 v00 = s0[0], v01 = s0[32];
        float4 v10 = s1[0], v11 = s1[32];
        a0.x += v00.x * i0; a0.y += v00.y * i0; a0.z += v00.z * i0; a0.w += v00.w * i0;
        a1.x += v01.x * i0; a1.y += v01.y * i0; a1.z += v01.z * i0; a1.w += v01.w * i0;
        a0.x += v10.x * i1; a0.y += v10.y * i1; a0.z += v10.z * i1; a0.w += v10.w * i1;
        a1.x += v11.x * i1; a1.y += v11.y * i1; a1.z += v11.z * i1; a1.w += v11.w * i1;
    }
    if (j < deg) {
        int p0 = g_eperm[beg + j];
        int c0 = p0 >> 3, t0 = p0 & 7;
        float i0 = 1.f / (float)cntp[t0];
        const float4* s0 = (const float4*)(Y + (size_t)c0 * (NET * C_DIM) + t0 * C_DIM) + lane;
        float4 v00 = s0[0], v01 = s0[32];
        a0.x += v00.x * i0; a0.y += v00.y * i0; a0.z += v00.z * i0; a0.w += v00.w * i0;
        a1.x += v01.x * i0; a1.y += v01.y * i0; a1.z += v01.z * i0; a1.w += v01.w * i0;
    }

    if (addResid) {
        const float4* rp = (const float4*)(resid + (size_t)w * C_DIM) + lane;
        float4 r0 = rp[0], r1 = rp[32];
        a0.x += r0.x; a0.y += r0.y; a0.z += r0.z; a0.w += r0.w;
        a1.x += r1.x; a1.y += r1.y; a1.z += r1.z; a1.w += r1.w;
    }
    float4* op = (float4*)(out + (size_t)w * C_DIM) + lane;
    op[0]  = a0;
    op[32] = a1;
}

// ---------------- launch ----------------
extern "C" void kernel_launch(void* const* d_in, const int* in_sizes, int n_in,
                              void* d_out, int out_size) {
    const float* x    = (const float*)d_in[0];
    const float* gn1w = (const float*)d_in[1];
    const float* gn1b = (const float*)d_in[2];
    const float* w1   = (const float*)d_in[3];
    const float* gn2w = (const float*)d_in[4];
    const float* gn2b = (const float*)d_in[5];
    const float* w2   = (const float*)d_in[6];
    const int*   eidx = (const int*)d_in[7];
    const int*   et   = (const int*)d_in[8];
    const int*   bid  = (const int*)d_in[9];

    int N = in_sizes[0] / C_DIM;
    int E = in_sizes[8];
    const int* erow = eidx;
    const int* ecol = eidx + E;

    float *p_h, *p_acc, *p_Y;
    cudaGetSymbolAddress((void**)&p_h,   g_h);
    cudaGetSymbolAddress((void**)&p_acc, g_acc);
    cudaGetSymbolAddress((void**)&p_Y,   g_Y);

    cudaFuncSetAttribute(k_gemm, cudaFuncAttributeMaxDynamicSharedMemorySize, GEMM_SMEM);

    int n7 = N * NET;
    int t4 = N * (C_DIM / 4);
    int gnBlocks = (N + NPB - 1) / NPB;
    int nbScan = (N + SCAN_B - 1) / SCAN_B;
    dim3 gemmGrid(NET * C_DIM / BN, (N + BM - 1) / BM);
    int gatherBlocks = (N + 7) / 8;   // 8 warps per 256-thread block

    // --- init + CSR build (edge structure shared by both convs) ---
    k_init<<<(n7 + 255) / 256, 256>>>(N, n7);
    k_bcount<<<(N + 255) / 256, 256>>>(bid, N);
    k_ecount2<<<(E + 255) / 256, 256>>>(erow, et, E);
    k_scan1<<<nbScan, 256>>>(N);
    k_scan2<<<1, 64>>>(nbScan);
    k_scan3<<<(N + 255) / 256, 256>>>(N);
    k_escatter<<<(E + 255) / 256, 256>>>(erow, ecol, et, E);

    // --- GN1 + silu ---
    k_gnstats<<<gnBlocks, 256>>>(x, bid, N);
    k_gnfinal<<<1, 256>>>();
    k_gn_silu<<<(t4 + 255) / 256, 256>>>(x, p_h, gn1w, gn1b, bid, N);

    // --- conv1: GEMM then CSR gather-mean (no atomics, no zeroing) ---
    k_gemm<<<gemmGrid, 256, GEMM_SMEM>>>(p_h, w1, p_Y, N);
    k_gather<<<gatherBlocks, 256>>>(p_Y, nullptr, p_acc, N, 0);

    // --- GN2 + silu ---
    k_zero_stats<<<1, 256>>>();
    k_gnstats<<<gnBlocks, 256>>>(p_acc, bid, N);
    k_gnfinal<<<1, 256>>>();
    k_gn_silu<<<(t4 + 255) / 256, 256>>>(p_acc, p_h, gn2w, gn2b, bid, N);

    // --- conv2 + fused residual ---
    k_gemm<<<gemmGrid, 256, GEMM_SMEM>>>(p_h, w2, p_Y, N);
    k_gather<<<gatherBlocks, 256>>>(p_Y, x, (float*)d_out, N, 1);
}

// round 7
// speedup vs baseline: 1.8475x; 1.3189x over previous
#include <cuda_runtime.h>
#include <cuda_fp16.h>
#include <stdint.h>

#define C_DIM   256
#define NGROUP  32
#define CPG     8
#define NET     7
#define NBATCH  8
#define GN_EPS  1e-5f
#define MAXN    100000
#define MAXE    1048576
#define NPB     128
#define SCAN_B  2048

// ---------------- scratch ----------------
__device__ __half  g_h  [(size_t)MAXN * C_DIM];          // 51.2 MB (fp16 GEMM input)
__device__ float   g_acc[(size_t)MAXN * C_DIM];          // conv1 output (fp32)
__device__ __half  g_Y  [(size_t)MAXN * NET * C_DIM];    // 358 MB fp16 intermediate
__device__ __half2 g_Wp1[NET * 128 * C_DIM];             // packed W1: [t][k/2][n] half2
__device__ __half2 g_Wp2[NET * 128 * C_DIM];
__device__ int     g_cnt[MAXN * NET];
__device__ int     g_rowcnt[MAXN];
__device__ int     g_offs[MAXN];
__device__ int     g_cur[MAXN];
__device__ int     g_blksum[64];
__device__ int     g_eperm[MAXE];
__device__ float   g_s1 [NBATCH * NGROUP];
__device__ float   g_s2 [NBATCH * NGROUP];
__device__ float   g_mean[NBATCH * NGROUP];
__device__ float   g_istd[NBATCH * NGROUP];
__device__ float   g_bcnt[NBATCH];

// ---------------- init ----------------
__global__ void k_init(int N, int n7) {
    int i = blockIdx.x * blockDim.x + threadIdx.x;
    if (i < n7) g_cnt[i] = 0;
    if (i < N) { g_rowcnt[i] = 0; g_cur[i] = 0; }
    if (i < NBATCH * NGROUP) { g_s1[i] = 0.f; g_s2[i] = 0.f; }
    if (i < NBATCH) g_bcnt[i] = 0.f;
}
__global__ void k_zero_stats() {
    int i = threadIdx.x;
    g_s1[i] = 0.f; g_s2[i] = 0.f;
}
__global__ void k_bcount(const int* __restrict__ bid, int N) {
    __shared__ int sc[NBATCH];
    if (threadIdx.x < NBATCH) sc[threadIdx.x] = 0;
    __syncthreads();
    int i = blockIdx.x * blockDim.x + threadIdx.x;
    if (i < N) atomicAdd(&sc[bid[i]], 1);
    __syncthreads();
    if (threadIdx.x < NBATCH && sc[threadIdx.x] > 0)
        atomicAdd(&g_bcnt[threadIdx.x], (float)sc[threadIdx.x]);
}

// ---------------- W pack: Wp[t][k2][n] = (W[t*256+2k2][n], W[t*256+2k2+1][n]) fp16 ----------------
__global__ void k_wpack(const float* __restrict__ W, __half2* __restrict__ Wp, int total) {
    int i = blockIdx.x * blockDim.x + threadIdx.x;
    if (i >= total) return;
    int t   = i >> 15;            // / (128*256)
    int rem = i & 32767;
    int k2  = rem >> 8, n = rem & 255;
    const float* base = W + ((size_t)(t * 256 + 2 * k2)) * C_DIM + n;
    Wp[i] = __floats2half2_rn(base[0], base[C_DIM]);
}

// ---------------- GN ----------------
__global__ void k_gnstats(const float* __restrict__ src, const int* __restrict__ bid, int N) {
    __shared__ int sbid[NPB];
    int n0 = blockIdx.x * NPB;
    int nmax = min(N - n0, NPB);
    for (int i = threadIdx.x; i < nmax; i += blockDim.x) sbid[i] = bid[n0 + i];
    __syncthreads();
    int c = threadIdx.x;
    int g = c >> 3;
    float ls1 = 0.f, ls2 = 0.f;
    int cur = sbid[0];
    for (int i = 0; i < nmax; ++i) {
        int b = sbid[i];
        if (b != cur) {
            atomicAdd(&g_s1[cur * NGROUP + g], ls1);
            atomicAdd(&g_s2[cur * NGROUP + g], ls2);
            ls1 = 0.f; ls2 = 0.f; cur = b;
        }
        float v = src[(size_t)(n0 + i) * C_DIM + c];
        ls1 += v; ls2 += v * v;
    }
    atomicAdd(&g_s1[cur * NGROUP + g], ls1);
    atomicAdd(&g_s2[cur * NGROUP + g], ls2);
}
__global__ void k_gnfinal() {
    int i = threadIdx.x;
    int b = i >> 5;
    float n  = g_bcnt[b] * (float)CPG;
    float ic = 1.0f / (n + GN_EPS);
    float s1 = g_s1[i], s2 = g_s2[i];
    float m  = s1 * ic;
    float var = ic * (s2 - 2.f * m * s1 + m * m * n);
    g_mean[i] = m;
    g_istd[i] = rsqrtf(var + GN_EPS);
}
// GN + silu, output fp16 (feeds the GEMM)
__global__ void k_gn_silu_h(const float* __restrict__ src, __half* __restrict__ dst,
                            const float* __restrict__ w, const float* __restrict__ bb,
                            const int* __restrict__ bid, int N) {
    int i = blockIdx.x * blockDim.x + threadIdx.x;    // float4 index
    int total = N * (C_DIM / 4);
    if (i >= total) return;
    int n  = i >> 6;
    int c4 = (i & 63) << 2;
    int b  = bid[n];
    int s  = b * NGROUP + (c4 >> 3);
    float m  = g_mean[s], is = g_istd[s];
    float4 xv = ((const float4*)src)[i];
    float4 wv = ((const float4*)w)[c4 >> 2];
    float4 bv = ((const float4*)bb)[c4 >> 2];
    float v0 = (xv.x - m) * is * wv.x + bv.x; v0 = v0 / (1.f + expf(-v0));
    float v1 = (xv.y - m) * is * wv.y + bv.y; v1 = v1 / (1.f + expf(-v1));
    float v2 = (xv.z - m) * is * wv.z + bv.z; v2 = v2 / (1.f + expf(-v2));
    float v3 = (xv.w - m) * is * wv.w + bv.w; v3 = v3 / (1.f + expf(-v3));
    __half2 h[2];
    h[0] = __floats2half2_rn(v0, v1);
    h[1] = __floats2half2_rn(v2, v3);
    *(uint2*)(dst + (size_t)n * C_DIM + c4) = *(uint2*)h;
}

// ---------------- CSR build ----------------
__global__ void k_ecount2(const int* __restrict__ erow, const int* __restrict__ et, int E) {
    int e = blockIdx.x * blockDim.x + threadIdx.x;
    if (e < E) {
        int r = erow[e];
        atomicAdd(&g_cnt[r * NET + et[e]], 1);
        atomicAdd(&g_rowcnt[r], 1);
    }
}
__global__ void k_scan1(int N) {
    __shared__ int sh[256];
    int base = blockIdx.x * SCAN_B;
    int tid = threadIdx.x;
    int vals[8];
    int s = 0;
    #pragma unroll
    for (int j = 0; j < 8; ++j) {
        int idx = base + tid * 8 + j;
        int v = (idx < N) ? g_rowcnt[idx] : 0;
        vals[j] = s;
        s += v;
    }
    sh[tid] = s;
    __syncthreads();
    for (int off = 1; off < 256; off <<= 1) {
        int t = (tid >= off) ? sh[tid - off] : 0;
        __syncthreads();
        sh[tid] += t;
        __syncthreads();
    }
    int tb = tid ? sh[tid - 1] : 0;
    #pragma unroll
    for (int j = 0; j < 8; ++j) {
        int idx = base + tid * 8 + j;
        if (idx < N) g_offs[idx] = tb + vals[j];
    }
    if (tid == 255) g_blksum[blockIdx.x] = sh[255];
}
__global__ void k_scan2(int nb) {
    __shared__ int sh[64];
    int t = threadIdx.x;
    sh[t] = (t < nb) ? g_blksum[t] : 0;
    __syncthreads();
    for (int off = 1; off < 64; off <<= 1) {
        int v = (t >= off) ? sh[t - off] : 0;
        __syncthreads();
        sh[t] += v;
        __syncthreads();
    }
    if (t < nb) g_blksum[t] = t ? sh[t - 1] : 0;
}
__global__ void k_scan3(int N) {
    int i = blockIdx.x * blockDim.x + threadIdx.x;
    if (i < N) g_offs[i] += g_blksum[i / SCAN_B];
}
__global__ void k_escatter(const int* __restrict__ erow, const int* __restrict__ ecol,
                           const int* __restrict__ et, int E) {
    int e = blockIdx.x * blockDim.x + threadIdx.x;
    if (e >= E) return;
    int r = erow[e];
    int pos = g_offs[r] + atomicAdd(&g_cur[r], 1);
    g_eperm[pos] = (ecol[e] << 3) | et[e];
}

// ---------------- fp16 tensor-core GEMM: Y[N,1792](fp16) = A[N,256](fp16) @ Wp ----------------
// mma.sync.m16n8k16 f16 with f32 accum. BM=128, BN=128, BK=32, double-buffered.
#define BM 128
#define BN 128
#define BK 32
#define ASU 768      // A buffer: 128 rows * 6 uint4 (48 halves incl pad)
#define BPU 528      // B buffer: 16 k2-rows * 33 uint4 (132 half2 incl pad)

__device__ __forceinline__ void mma_f16(float* d, const uint32_t* a, uint32_t b0, uint32_t b1) {
    asm volatile("mma.sync.aligned.m16n8k16.row.col.f32.f16.f16.f32 "
        "{%0,%1,%2,%3}, {%4,%5,%6,%7}, {%8,%9}, {%0,%1,%2,%3};\n"
        : "+f"(d[0]), "+f"(d[1]), "+f"(d[2]), "+f"(d[3])
        : "r"(a[0]), "r"(a[1]), "r"(a[2]), "r"(a[3]), "r"(b0), "r"(b1));
}

__global__ __launch_bounds__(256, 2)
void k_gemm_h(const __half* __restrict__ A, const __half2* __restrict__ Wp,
              __half* __restrict__ Y, int N) {
    __shared__ __align__(16) uint4 AsU[2][ASU];
    __shared__ __align__(16) uint4 BpU[2][BPU];

    int n0 = blockIdx.x * BN;            // 0..1791 step 128
    int m0 = blockIdx.y * BM;
    int t  = n0 >> 8;
    int o0 = n0 & 255;                   // 0 or 128 (n offset)
    // global B, packed [t][k2][n] half2; as uint4 rows of 64
    const uint4* gB = (const uint4*)Wp + (size_t)(t * 128) * 64 + (o0 >> 2);

    int tid  = threadIdx.x;
    int warp = tid >> 5, lane = tid & 31;
    int wm = warp >> 1, wn = warp & 1;
    int mBase = wm * 32, nBase = wn * 64;
    int grp = lane >> 2, tig = lane & 3;

    float acc[2][8][4];
    #pragma unroll
    for (int i = 0; i < 2; ++i)
        #pragma unroll
        for (int j = 0; j < 8; ++j)
            #pragma unroll
            for (int q = 0; q < 4; ++q) acc[i][j][q] = 0.f;

    uint4 aR[2], bR[2];

    auto loadRegs = [&](int kb) {
        #pragma unroll
        for (int p = 0; p < 2; ++p) {
            int idx = tid + p * 256;         // 0..511
            int row = idx >> 2, q = idx & 3; // q: uint4 (8 halves) within 32-half row
            if (m0 + row < N)
                aR[p] = *(const uint4*)(A + (size_t)(m0 + row) * C_DIM + kb + q * 8);
            else
                aR[p] = make_uint4(0u, 0u, 0u, 0u);
        }
        int kb2 = kb >> 1;
        #pragma unroll
        for (int p = 0; p < 2; ++p) {
            int idx = tid + p * 256;         // 0..511
            int row = idx >> 5, u = idx & 31;
            bR[p] = gB[(size_t)(kb2 + row) * 64 + u];
        }
    };

    auto storeSmem = [&](int buf) {
        #pragma unroll
        for (int p = 0; p < 2; ++p) {
            int idx = tid + p * 256;
            int row = idx >> 2, q = idx & 3;
            AsU[buf][row * 6 + q] = aR[p];
        }
        #pragma unroll
        for (int p = 0; p < 2; ++p) {
            int idx = tid + p * 256;
            int row = idx >> 5, u = idx & 31;
            BpU[buf][row * 33 + u] = bR[p];
        }
    };

    auto compute = [&](int buf) {
        const __half*  Ah = (const __half*)&AsU[buf][0];     // row stride 48 halves
        const uint32_t* Bh = (const uint32_t*)&BpU[buf][0];  // row stride 132 half2
        #pragma unroll
        for (int ks = 0; ks < 2; ++ks) {
            int k0 = ks * 16;
            uint32_t a[2][4];
            #pragma unroll
            for (int im = 0; im < 2; ++im) {
                int r = mBase + im * 16 + grp;
                a[im][0] = *(const uint32_t*)(Ah + (r    ) * 48 + k0 + 2 * tig);
                a[im][1] = *(const uint32_t*)(Ah + (r + 8) * 48 + k0 + 2 * tig);
                a[im][2] = *(const uint32_t*)(Ah + (r    ) * 48 + k0 + 2 * tig + 8);
                a[im][3] = *(const uint32_t*)(Ah + (r + 8) * 48 + k0 + 2 * tig + 8);
            }
            #pragma unroll
            for (int in = 0; in < 8; ++in) {
                int nn = nBase + in * 8 + grp;
                uint32_t b0 = Bh[(ks * 8 + tig    ) * 132 + nn];
                uint32_t b1 = Bh[(ks * 8 + tig + 4) * 132 + nn];
                mma_f16(acc[0][in], a[0], b0, b1);
                mma_f16(acc[1][in], a[1], b0, b1);
            }
        }
    };

    loadRegs(0);
    storeSmem(0);
    __syncthreads();
    #pragma unroll
    for (int it = 0; it < 8; ++it) {
        if (it < 7) loadRegs((it + 1) * BK);
        compute(it & 1);
        if (it < 7) {
            storeSmem((it + 1) & 1);
            __syncthreads();
        }
    }

    // epilogue: fp16 Y
    #pragma unroll
    for (int im = 0; im < 2; ++im) {
        int r0 = m0 + mBase + im * 16 + grp;
        #pragma unroll
        for (int in = 0; in < 8; ++in) {
            int cc = n0 + nBase + in * 8 + tig * 2;
            if (r0 < N) {
                __half2 h = __floats2half2_rn(acc[im][in][0], acc[im][in][1]);
                *(__half2*)(Y + (size_t)r0 * (NET * C_DIM) + cc) = h;
            }
            if (r0 + 8 < N) {
                __half2 h = __floats2half2_rn(acc[im][in][2], acc[im][in][3]);
                *(__half2*)(Y + (size_t)(r0 + 8) * (NET * C_DIM) + cc) = h;
            }
        }
    }
}

// ---------------- gather: one warp per row, fp16 Y, zero atomics ----------------
__global__ void k_gather(const __half* __restrict__ Y, const float* __restrict__ resid,
                         float* __restrict__ out, int N, int addResid) {
    int w = (blockIdx.x * blockDim.x + threadIdx.x) >> 5;
    int lane = threadIdx.x & 31;
    if (w >= N) return;
    int beg = g_offs[w];
    int deg = g_rowcnt[w];
    const int* cntp = &g_cnt[w * NET];

    float acc[8] = {0.f, 0.f, 0.f, 0.f, 0.f, 0.f, 0.f, 0.f};

    for (int j = 0; j < deg; ++j) {
        int p = g_eperm[beg + j];
        int c = p >> 3, t = p & 7;
        float inv = 1.f / (float)cntp[t];
        const uint4* src = (const uint4*)(Y + (size_t)c * (NET * C_DIM) + t * C_DIM) + lane;
        uint4 v = *src;                       // 8 halves
        const __half2* h = (const __half2*)&v;
        #pragma unroll
        for (int q = 0; q < 4; ++q) {
            float2 f = __half22float2(h[q]);
            acc[q * 2 + 0] += f.x * inv;
            acc[q * 2 + 1] += f.y * inv;
        }
    }

    float* orow = out + (size_t)w * C_DIM + lane * 8;
    if (addResid) {
        const float* rp = resid + (size_t)w * C_DIM + lane * 8;
        float4 r0 = *(const float4*)rp, r1 = *(const float4*)(rp + 4);
        acc[0] += r0.x; acc[1] += r0.y; acc[2] += r0.z; acc[3] += r0.w;
        acc[4] += r1.x; acc[5] += r1.y; acc[6] += r1.z; acc[7] += r1.w;
    }
    *(float4*)orow       = make_float4(acc[0], acc[1], acc[2], acc[3]);
    *(float4*)(orow + 4) = make_float4(acc[4], acc[5], acc[6], acc[7]);
}

// ---------------- launch ----------------
extern "C" void kernel_launch(void* const* d_in, const int* in_sizes, int n_in,
                              void* d_out, int out_size) {
    const float* x    = (const float*)d_in[0];
    const float* gn1w = (const float*)d_in[1];
    const float* gn1b = (const float*)d_in[2];
    const float* w1   = (const float*)d_in[3];
    const float* gn2w = (const float*)d_in[4];
    const float* gn2b = (const float*)d_in[5];
    const float* w2   = (const float*)d_in[6];
    const int*   eidx = (const int*)d_in[7];
    const int*   et   = (const int*)d_in[8];
    const int*   bid  = (const int*)d_in[9];

    int N = in_sizes[0] / C_DIM;
    int E = in_sizes[8];
    const int* erow = eidx;
    const int* ecol = eidx + E;

    float *p_acc;
    __half *p_h, *p_Y;
    __half2 *p_Wp1, *p_Wp2;
    cudaGetSymbolAddress((void**)&p_h,   g_h);
    cudaGetSymbolAddress((void**)&p_acc, g_acc);
    cudaGetSymbolAddress((void**)&p_Y,   g_Y);
    cudaGetSymbolAddress((void**)&p_Wp1, g_Wp1);
    cudaGetSymbolAddress((void**)&p_Wp2, g_Wp2);

    int n7 = N * NET;
    int t4 = N * (C_DIM / 4);
    int gnBlocks = (N + NPB - 1) / NPB;
    int nbScan = (N + SCAN_B - 1) / SCAN_B;
    dim3 gemmGrid(NET * C_DIM / BN, (N + BM - 1) / BM);
    int gatherBlocks = (N + 7) / 8;
    int wpTotal = NET * 128 * C_DIM;

    // --- init + W pack + CSR build ---
    k_init<<<(n7 + 255) / 256, 256>>>(N, n7);
    k_wpack<<<(wpTotal + 255) / 256, 256>>>(w1, p_Wp1, wpTotal);
    k_wpack<<<(wpTotal + 255) / 256, 256>>>(w2, p_Wp2, wpTotal);
    k_bcount<<<(N + 255) / 256, 256>>>(bid, N);
    k_ecount2<<<(E + 255) / 256, 256>>>(erow, et, E);
    k_scan1<<<nbScan, 256>>>(N);
    k_scan2<<<1, 64>>>(nbScan);
    k_scan3<<<(N + 255) / 256, 256>>>(N);
    k_escatter<<<(E + 255) / 256, 256>>>(erow, ecol, et, E);

    // --- GN1 + silu (fp16 out) ---
    k_gnstats<<<gnBlocks, 256>>>(x, bid, N);
    k_gnfinal<<<1, 256>>>();
    k_gn_silu_h<<<(t4 + 255) / 256, 256>>>(x, p_h, gn1w, gn1b, bid, N);

    // --- conv1: fp16 GEMM then CSR gather-mean ---
    k_gemm_h<<<gemmGrid, 256>>>(p_h, p_Wp1, p_Y, N);
    k_gather<<<gatherBlocks, 256>>>(p_Y, nullptr, p_acc, N, 0);

    // --- GN2 + silu (fp16 out) ---
    k_zero_stats<<<1, 256>>>();
    k_gnstats<<<gnBlocks, 256>>>(p_acc, bid, N);
    k_gnfinal<<<1, 256>>>();
    k_gn_silu_h<<<(t4 + 255) / 256, 256>>>(p_acc, p_h, gn2w, gn2b, bid, N);

    // --- conv2 + fused residual ---
    k_gemm_h<<<gemmGrid, 256>>>(p_h, p_Wp2, p_Y, N);
    k_gather<<<gatherBlocks, 256>>>(p_Y, x, (float*)d_out, N, 1);
}

// round 8
// speedup vs baseline: 2.5779x; 1.3953x over previous
#include <cuda_runtime.h>
#include <cuda_fp16.h>
#include <stdint.h>

#define C_DIM   256
#define NGROUP  32
#define CPG     8
#define NET     7
#define NBATCH  8
#define GN_EPS  1e-5f
#define MAXN    100000
#define MAXE    1048576
#define NPB     128
#define SCAN_B  2048

// ---------------- scratch ----------------
__device__ __half  g_h  [(size_t)MAXN * C_DIM];          // fp16 GEMM input
__device__ float   g_acc[(size_t)MAXN * C_DIM];          // conv1 output (fp32)
__device__ __half  g_Y  [(size_t)MAXN * NET * C_DIM];    // fp16 intermediate
__device__ __half  g_Wb1[NET * C_DIM * C_DIM];           // packed W1: [t][n][k] fp16
__device__ __half  g_Wb2[NET * C_DIM * C_DIM];
__device__ int     g_cnt[MAXN * NET];
__device__ int     g_rowcnt[MAXN];
__device__ int     g_offs[MAXN];
__device__ int     g_cur[MAXN];
__device__ int     g_blksum[64];
__device__ int     g_eperm[MAXE];
__device__ float   g_s1 [NBATCH * NGROUP];
__device__ float   g_s2 [NBATCH * NGROUP];
__device__ float   g_mean[NBATCH * NGROUP];
__device__ float   g_istd[NBATCH * NGROUP];
__device__ float   g_bcnt[NBATCH];

// ---------------- init ----------------
__global__ void k_init(int N, int n7) {
    int i = blockIdx.x * blockDim.x + threadIdx.x;
    if (i < n7) g_cnt[i] = 0;
    if (i < N) { g_rowcnt[i] = 0; g_cur[i] = 0; }
    if (i < NBATCH * NGROUP) { g_s1[i] = 0.f; g_s2[i] = 0.f; }
    if (i < NBATCH) g_bcnt[i] = 0.f;
}
__global__ void k_zero_stats() {
    int i = threadIdx.x;
    g_s1[i] = 0.f; g_s2[i] = 0.f;
}
__global__ void k_bcount(const int* __restrict__ bid, int N) {
    __shared__ int sc[NBATCH];
    if (threadIdx.x < NBATCH) sc[threadIdx.x] = 0;
    __syncthreads();
    int i = blockIdx.x * blockDim.x + threadIdx.x;
    if (i < N) atomicAdd(&sc[bid[i]], 1);
    __syncthreads();
    if (threadIdx.x < NBATCH && sc[threadIdx.x] > 0)
        atomicAdd(&g_bcnt[threadIdx.x], (float)sc[threadIdx.x]);
}

// ---------------- W pack+transpose: Wb[t][n][k] = fp16(W[(t*256+k)*256 + n]) ----------------
__global__ void k_wpackT(const float* __restrict__ W, __half* __restrict__ Wb) {
    __shared__ float tile[32][33];
    int t = blockIdx.z;
    int k0 = blockIdx.x * 32, n0 = blockIdx.y * 32;
    for (int j = threadIdx.y; j < 32; j += 8)
        tile[j][threadIdx.x] = W[(size_t)(t * 256 + k0 + j) * C_DIM + n0 + threadIdx.x];
    __syncthreads();
    for (int j = threadIdx.y; j < 32; j += 8)
        Wb[((size_t)t * 256 + n0 + j) * C_DIM + k0 + threadIdx.x] =
            __float2half_rn(tile[threadIdx.x][j]);
}

// ---------------- GN ----------------
__global__ void k_gnstats(const float* __restrict__ src, const int* __restrict__ bid, int N) {
    __shared__ int sbid[NPB];
    int n0 = blockIdx.x * NPB;
    int nmax = min(N - n0, NPB);
    for (int i = threadIdx.x; i < nmax; i += blockDim.x) sbid[i] = bid[n0 + i];
    __syncthreads();
    int c = threadIdx.x;
    int g = c >> 3;
    float ls1 = 0.f, ls2 = 0.f;
    int cur = sbid[0];
    for (int i = 0; i < nmax; ++i) {
        int b = sbid[i];
        if (b != cur) {
            atomicAdd(&g_s1[cur * NGROUP + g], ls1);
            atomicAdd(&g_s2[cur * NGROUP + g], ls2);
            ls1 = 0.f; ls2 = 0.f; cur = b;
        }
        float v = src[(size_t)(n0 + i) * C_DIM + c];
        ls1 += v; ls2 += v * v;
    }
    atomicAdd(&g_s1[cur * NGROUP + g], ls1);
    atomicAdd(&g_s2[cur * NGROUP + g], ls2);
}
__global__ void k_gnfinal() {
    int i = threadIdx.x;
    int b = i >> 5;
    float n  = g_bcnt[b] * (float)CPG;
    float ic = 1.0f / (n + GN_EPS);
    float s1 = g_s1[i], s2 = g_s2[i];
    float m  = s1 * ic;
    float var = ic * (s2 - 2.f * m * s1 + m * m * n);
    g_mean[i] = m;
    g_istd[i] = rsqrtf(var + GN_EPS);
}
__global__ void k_gn_silu_h(const float* __restrict__ src, __half* __restrict__ dst,
                            const float* __restrict__ w, const float* __restrict__ bb,
                            const int* __restrict__ bid, int N) {
    int i = blockIdx.x * blockDim.x + threadIdx.x;
    int total = N * (C_DIM / 4);
    if (i >= total) return;
    int n  = i >> 6;
    int c4 = (i & 63) << 2;
    int b  = bid[n];
    int s  = b * NGROUP + (c4 >> 3);
    float m  = g_mean[s], is = g_istd[s];
    float4 xv = ((const float4*)src)[i];
    float4 wv = ((const float4*)w)[c4 >> 2];
    float4 bv = ((const float4*)bb)[c4 >> 2];
    float v0 = (xv.x - m) * is * wv.x + bv.x; v0 = v0 / (1.f + expf(-v0));
    float v1 = (xv.y - m) * is * wv.y + bv.y; v1 = v1 / (1.f + expf(-v1));
    float v2 = (xv.z - m) * is * wv.z + bv.z; v2 = v2 / (1.f + expf(-v2));
    float v3 = (xv.w - m) * is * wv.w + bv.w; v3 = v3 / (1.f + expf(-v3));
    __half2 h[2];
    h[0] = __floats2half2_rn(v0, v1);
    h[1] = __floats2half2_rn(v2, v3);
    *(uint2*)(dst + (size_t)n * C_DIM + c4) = *(uint2*)h;
}

// ---------------- CSR build ----------------
__global__ void k_ecount2(const int* __restrict__ erow, const int* __restrict__ et, int E) {
    int e = blockIdx.x * blockDim.x + threadIdx.x;
    if (e < E) {
        int r = erow[e];
        atomicAdd(&g_cnt[r * NET + et[e]], 1);
        atomicAdd(&g_rowcnt[r], 1);
    }
}
__global__ void k_scan1(int N) {
    __shared__ int sh[256];
    int base = blockIdx.x * SCAN_B;
    int tid = threadIdx.x;
    int vals[8];
    int s = 0;
    #pragma unroll
    for (int j = 0; j < 8; ++j) {
        int idx = base + tid * 8 + j;
        int v = (idx < N) ? g_rowcnt[idx] : 0;
        vals[j] = s;
        s += v;
    }
    sh[tid] = s;
    __syncthreads();
    for (int off = 1; off < 256; off <<= 1) {
        int t = (tid >= off) ? sh[tid - off] : 0;
        __syncthreads();
        sh[tid] += t;
        __syncthreads();
    }
    int tb = tid ? sh[tid - 1] : 0;
    #pragma unroll
    for (int j = 0; j < 8; ++j) {
        int idx = base + tid * 8 + j;
        if (idx < N) g_offs[idx] = tb + vals[j];
    }
    if (tid == 255) g_blksum[blockIdx.x] = sh[255];
}
__global__ void k_scan2(int nb) {
    __shared__ int sh[64];
    int t = threadIdx.x;
    sh[t] = (t < nb) ? g_blksum[t] : 0;
    __syncthreads();
    for (int off = 1; off < 64; off <<= 1) {
        int v = (t >= off) ? sh[t - off] : 0;
        __syncthreads();
        sh[t] += v;
        __syncthreads();
    }
    if (t < nb) g_blksum[t] = t ? sh[t - 1] : 0;
}
__global__ void k_scan3(int N) {
    int i = blockIdx.x * blockDim.x + threadIdx.x;
    if (i < N) g_offs[i] += g_blksum[i / SCAN_B];
}
__global__ void k_escatter(const int* __restrict__ erow, const int* __restrict__ ecol,
                           const int* __restrict__ et, int E) {
    int e = blockIdx.x * blockDim.x + threadIdx.x;
    if (e >= E) return;
    int r = erow[e];
    int pos = g_offs[r] + atomicAdd(&g_cur[r], 1);
    g_eperm[pos] = (ecol[e] << 3) | et[e];
}

// ---------------- fp16 GEMM, cp.async 3-stage + ldmatrix ----------------
#define BM 128
#define BN 128
#define BK 32
#define KSTR 40                 // smem row stride in halves (conflict-free ldmatrix phases)
#define TILE_B (128 * KSTR * 2) // 10240 bytes per operand tile
#define STAGE_B (2 * TILE_B)
#define NSTAGE 3
#define EPS_LD 136              // epilogue smem row stride (halves)

__device__ __forceinline__ void mma_f16(float* d, const uint32_t* a, uint32_t b0, uint32_t b1) {
    asm volatile("mma.sync.aligned.m16n8k16.row.col.f32.f16.f16.f32 "
        "{%0,%1,%2,%3}, {%4,%5,%6,%7}, {%8,%9}, {%0,%1,%2,%3};\n"
        : "+f"(d[0]), "+f"(d[1]), "+f"(d[2]), "+f"(d[3])
        : "r"(a[0]), "r"(a[1]), "r"(a[2]), "r"(a[3]), "r"(b0), "r"(b1));
}
__device__ __forceinline__ void ldsm_x4(uint32_t* r, uint32_t addr) {
    asm volatile("ldmatrix.sync.aligned.m8n8.x4.shared.b16 {%0,%1,%2,%3}, [%4];\n"
        : "=r"(r[0]), "=r"(r[1]), "=r"(r[2]), "=r"(r[3]) : "r"(addr));
}

__global__ __launch_bounds__(256, 2)
void k_gemm_h(const __half* __restrict__ A, const __half* __restrict__ Wb,
              __half* __restrict__ Y, int N) {
    __shared__ __align__(16) char sm[NSTAGE * STAGE_B];   // 61440 B

    int tid  = threadIdx.x;
    int warp = tid >> 5, lane = tid & 31;
    int n0 = blockIdx.x * BN;
    int m0 = blockIdx.y * BM;
    int t  = n0 >> 8;
    int o0 = n0 & 255;
    const __half* gB = Wb + ((size_t)t * 256 + o0) * C_DIM;   // [n][k] rows

    int wm = warp >> 1, wn = warp & 1;
    int mBase = wm * 32, nBase = wn * 64;
    int grp = lane >> 2, tig = lane & 3;
    int mi = lane >> 3, lr = lane & 7;

    uint32_t sbase = (uint32_t)__cvta_generic_to_shared(sm);

    float acc[2][8][4];
    #pragma unroll
    for (int i = 0; i < 2; ++i)
        #pragma unroll
        for (int j = 0; j < 8; ++j)
            #pragma unroll
            for (int q = 0; q < 4; ++q) acc[i][j][q] = 0.f;

    int cRowA = tid >> 2, cQ = tid & 3;        // copy assignment (row, 16B chunk)
    int cRowA2 = cRowA + 64;                   // second chunk rows 64..127

    auto issue = [&](int st, int kb) {
        uint32_t sa = sbase + st * STAGE_B;
        uint32_t sb = sa + TILE_B;
        // A tile: 128 rows x 64B
        {
            uint32_t d0 = sa + cRowA * (KSTR * 2) + cQ * 16;
            const __half* s0 = A + (size_t)(m0 + cRowA) * C_DIM + kb + cQ * 8;
            int z0 = (m0 + cRowA < N) ? 16 : 0;
            const __half* p0 = z0 ? s0 : A;
            asm volatile("cp.async.cg.shared.global [%0], [%1], 16, %2;\n"
                :: "r"(d0), "l"(p0), "r"(z0) : "memory");
            uint32_t d1 = sa + cRowA2 * (KSTR * 2) + cQ * 16;
            const __half* s1 = A + (size_t)(m0 + cRowA2) * C_DIM + kb + cQ * 8;
            int z1 = (m0 + cRowA2 < N) ? 16 : 0;
            const __half* p1 = z1 ? s1 : A;
            asm volatile("cp.async.cg.shared.global [%0], [%1], 16, %2;\n"
                :: "r"(d1), "l"(p1), "r"(z1) : "memory");
        }
        // B tile: 128 n-rows x 64B
        {
            uint32_t d0 = sb + cRowA * (KSTR * 2) + cQ * 16;
            const __half* s0 = gB + (size_t)cRowA * C_DIM + kb + cQ * 8;
            asm volatile("cp.async.cg.shared.global [%0], [%1], 16, 16;\n"
                :: "r"(d0), "l"(s0) : "memory");
            uint32_t d1 = sb + cRowA2 * (KSTR * 2) + cQ * 16;
            const __half* s1 = gB + (size_t)cRowA2 * C_DIM + kb + cQ * 8;
            asm volatile("cp.async.cg.shared.global [%0], [%1], 16, 16;\n"
                :: "r"(d1), "l"(s1) : "memory");
        }
        asm volatile("cp.async.commit_group;\n" ::: "memory");
    };

    auto compute = [&](int st) {
        uint32_t sa = sbase + st * STAGE_B;
        uint32_t sb = sa + TILE_B;
        #pragma unroll
        for (int ks = 0; ks < 2; ++ks) {
            int k0 = ks * 16;
            uint32_t a[2][4];
            #pragma unroll
            for (int im = 0; im < 2; ++im) {
                int row = mBase + im * 16 + ((mi & 1) << 3) + lr;
                int col = k0 + ((mi >> 1) << 3);
                ldsm_x4(a[im], sa + (uint32_t)(row * KSTR + col) * 2);
            }
            #pragma unroll
            for (int nb = 0; nb < 4; ++nb) {
                uint32_t b[4];
                int row = nBase + nb * 16 + ((mi >> 1) << 3) + lr;
                int col = k0 + ((mi & 1) << 3);
                ldsm_x4(b, sb + (uint32_t)(row * KSTR + col) * 2);
                mma_f16(acc[0][nb * 2],     a[0], b[0], b[1]);
                mma_f16(acc[1][nb * 2],     a[1], b[0], b[1]);
                mma_f16(acc[0][nb * 2 + 1], a[0], b[2], b[3]);
                mma_f16(acc[1][nb * 2 + 1], a[1], b[2], b[3]);
            }
        }
    };

    issue(0, 0);
    issue(1, BK);
    #pragma unroll
    for (int it = 0; it < 8; ++it) {
        if (it + 2 < 8) {
            asm volatile("cp.async.wait_group 1;\n" ::: "memory");
        } else {
            asm volatile("cp.async.wait_group 0;\n" ::: "memory");
        }
        __syncthreads();
        if (it + 2 < 8) issue((it + 2) % 3, (it + 2) * BK);
        compute(it % 3);
    }

    // ---- epilogue: stage via smem, coalesced uint4 stores ----
    __syncthreads();
    __half* ep = (__half*)sm;
    #pragma unroll
    for (int im = 0; im < 2; ++im) {
        int r = mBase + im * 16 + grp;
        #pragma unroll
        for (int in = 0; in < 8; ++in) {
            int cc = nBase + in * 8 + tig * 2;
            *(__half2*)(ep + r * EPS_LD + cc) =
                __floats2half2_rn(acc[im][in][0], acc[im][in][1]);
            *(__half2*)(ep + (r + 8) * EPS_LD + cc) =
                __floats2half2_rn(acc[im][in][2], acc[im][in][3]);
        }
    }
    __syncthreads();
    #pragma unroll
    for (int j = 0; j < 8; ++j) {
        int idx = tid + j * 256;          // 0..2047
        int row = idx >> 4, u = idx & 15;
        if (m0 + row < N)
            *(uint4*)(Y + (size_t)(m0 + row) * (NET * C_DIM) + n0 + u * 8) =
                *(const uint4*)(ep + row * EPS_LD + u * 8);
    }
}

// ---------------- gather: one warp per row, fp16 Y, zero atomics ----------------
__global__ void k_gather(const __half* __restrict__ Y, const float* __restrict__ resid,
                         float* __restrict__ out, int N, int addResid) {
    int w = (blockIdx.x * blockDim.x + threadIdx.x) >> 5;
    int lane = threadIdx.x & 31;
    if (w >= N) return;
    int beg = g_offs[w];
    int deg = g_rowcnt[w];
    const int* cntp = &g_cnt[w * NET];

    float acc[8] = {0.f, 0.f, 0.f, 0.f, 0.f, 0.f, 0.f, 0.f};

    for (int j = 0; j < deg; ++j) {
        int p = g_eperm[beg + j];
        int c = p >> 3, t = p & 7;
        float inv = 1.f / (float)cntp[t];
        const uint4* src = (const uint4*)(Y + (size_t)c * (NET * C_DIM) + t * C_DIM) + lane;
        uint4 v = *src;
        const __half2* h = (const __half2*)&v;
        #pragma unroll
        for (int q = 0; q < 4; ++q) {
            float2 f = __half22float2(h[q]);
            acc[q * 2 + 0] += f.x * inv;
            acc[q * 2 + 1] += f.y * inv;
        }
    }

    float* orow = out + (size_t)w * C_DIM + lane * 8;
    if (addResid) {
        const float* rp = resid + (size_t)w * C_DIM + lane * 8;
        float4 r0 = *(const float4*)rp, r1 = *(const float4*)(rp + 4);
        acc[0] += r0.x; acc[1] += r0.y; acc[2] += r0.z; acc[3] += r0.w;
        acc[4] += r1.x; acc[5] += r1.y; acc[6] += r1.z; acc[7] += r1.w;
    }
    *(float4*)orow       = make_float4(acc[0], acc[1], acc[2], acc[3]);
    *(float4*)(orow + 4) = make_float4(acc[4], acc[5], acc[6], acc[7]);
}

// ---------------- launch ----------------
extern "C" void kernel_launch(void* const* d_in, const int* in_sizes, int n_in,
                              void* d_out, int out_size) {
    const float* x    = (const float*)d_in[0];
    const float* gn1w = (const float*)d_in[1];
    const float* gn1b = (const float*)d_in[2];
    const float* w1   = (const float*)d_in[3];
    const float* gn2w = (const float*)d_in[4];
    const float* gn2b = (const float*)d_in[5];
    const float* w2   = (const float*)d_in[6];
    const int*   eidx = (const int*)d_in[7];
    const int*   et   = (const int*)d_in[8];
    const int*   bid  = (const int*)d_in[9];

    int N = in_sizes[0] / C_DIM;
    int E = in_sizes[8];
    const int* erow = eidx;
    const int* ecol = eidx + E;

    float *p_acc;
    __half *p_h, *p_Y, *p_Wb1, *p_Wb2;
    cudaGetSymbolAddress((void**)&p_h,   g_h);
    cudaGetSymbolAddress((void**)&p_acc, g_acc);
    cudaGetSymbolAddress((void**)&p_Y,   g_Y);
    cudaGetSymbolAddress((void**)&p_Wb1, g_Wb1);
    cudaGetSymbolAddress((void**)&p_Wb2, g_Wb2);

    int n7 = N * NET;
    int t4 = N * (C_DIM / 4);
    int gnBlocks = (N + NPB - 1) / NPB;
    int nbScan = (N + SCAN_B - 1) / SCAN_B;
    dim3 gemmGrid(NET * C_DIM / BN, (N + BM - 1) / BM);
    int gatherBlocks = (N + 7) / 8;
    dim3 wtGrid(8, 8, NET), wtBlock(32, 8);

    // --- init + W pack + CSR build ---
    k_init<<<(n7 + 255) / 256, 256>>>(N, n7);
    k_wpackT<<<wtGrid, wtBlock>>>(w1, p_Wb1);
    k_wpackT<<<wtGrid, wtBlock>>>(w2, p_Wb2);
    k_bcount<<<(N + 255) / 256, 256>>>(bid, N);
    k_ecount2<<<(E + 255) / 256, 256>>>(erow, et, E);
    k_scan1<<<nbScan, 256>>>(N);
    k_scan2<<<1, 64>>>(nbScan);
    k_scan3<<<(N + 255) / 256, 256>>>(N);
    k_escatter<<<(E + 255) / 256, 256>>>(erow, ecol, et, E);

    // --- GN1 + silu (fp16 out) ---
    k_gnstats<<<gnBlocks, 256>>>(x, bid, N);
    k_gnfinal<<<1, 256>>>();
    k_gn_silu_h<<<(t4 + 255) / 256, 256>>>(x, p_h, gn1w, gn1b, bid, N);

    // --- conv1: fp16 GEMM then CSR gather-mean ---
    k_gemm_h<<<gemmGrid, 256>>>(p_h, p_Wb1, p_Y, N);
    k_gather<<<gatherBlocks, 256>>>(p_Y, nullptr, p_acc, N, 0);

    // --- GN2 + silu (fp16 out) ---
    k_zero_stats<<<1, 256>>>();
    k_gnstats<<<gnBlocks, 256>>>(p_acc, bid, N);
    k_gnfinal<<<1, 256>>>();
    k_gn_silu_h<<<(t4 + 255) / 256, 256>>>(p_acc, p_h, gn2w, gn2b, bid, N);

    // --- conv2 + fused residual ---
    k_gemm_h<<<gemmGrid, 256>>>(p_h, p_Wb2, p_Y, N);
    k_gather<<<gatherBlocks, 256>>>(p_Y, x, (float*)d_out, N, 1);
}

// round 9
// speedup vs baseline: 3.1214x; 1.2108x over previous
#include <cuda_runtime.h>
#include <cuda_fp16.h>
#include <stdint.h>

#define C_DIM   256
#define NGROUP  32
#define CPG     8
#define NET     7
#define NBATCH  8
#define GN_EPS  1e-5f
#define MAXN    100000
#define MAXE    1048576
#define N7MAX   (MAXN * NET)
#define NPB     128
#define SCAN_B  2048

// ---------------- scratch ----------------
__device__ __half  g_h  [(size_t)MAXN * C_DIM];            // fp16 GEMM input
__device__ float   g_acc[(size_t)MAXN * C_DIM];            // conv1 output (fp32)
__device__ __half  g_Y  [(size_t)(N7MAX + 1024) * C_DIM];  // compacted fp16 intermediate
__device__ __half  g_Wb1[NET * C_DIM * C_DIM];             // packed W1: [t][n][k] fp16
__device__ __half  g_Wb2[NET * C_DIM * C_DIM];
__device__ int     g_cnt[MAXN * NET];      // per (row, type) in-degree
__device__ int     g_rowcnt[MAXN];
__device__ int     g_offs[MAXN];
__device__ int     g_cur[MAXN];
__device__ int     g_blksum[64];
__device__ int     g_eperm[MAXE];          // (pos<<3) | type
// --- compaction state ---
__device__ int     g_need[N7MAX];          // keyed t*N + c
__device__ int     g_cpos[N7MAX];          // flat exclusive scan of indicator
__device__ int     g_blksum2[512];
__device__ int     g_pos [N7MAX];          // (t,c) -> compacted row
__device__ int     g_clist[N7MAX + 1024];  // compacted row -> column c (-1 = pad)
__device__ int     g_tpadA[8];             // padded segment starts (tpadA[7] = mtotal)
__device__ int     g_tstart[8];            // unpadded segment starts
__device__ int     g_mtotal;
// --- GN state ---
__device__ float   g_s1 [NBATCH * NGROUP];
__device__ float   g_s2 [NBATCH * NGROUP];
__device__ float   g_mean[NBATCH * NGROUP];
__device__ float   g_istd[NBATCH * NGROUP];
__device__ float   g_bcnt[NBATCH];

// ---------------- init ----------------
__global__ void k_init(int N, int n7) {
    int i = blockIdx.x * blockDim.x + threadIdx.x;
    if (i < n7) { g_cnt[i] = 0; g_need[i] = 0; }
    if (i < n7 + 1024) g_clist[i] = -1;
    if (i < N) { g_rowcnt[i] = 0; g_cur[i] = 0; }
    if (i < NBATCH * NGROUP) { g_s1[i] = 0.f; g_s2[i] = 0.f; }
    if (i < NBATCH) g_bcnt[i] = 0.f;
}
__global__ void k_zero_stats() {
    int i = threadIdx.x;
    g_s1[i] = 0.f; g_s2[i] = 0.f;
}
__global__ void k_bcount(const int* __restrict__ bid, int N) {
    __shared__ int sc[NBATCH];
    if (threadIdx.x < NBATCH) sc[threadIdx.x] = 0;
    __syncthreads();
    int i = blockIdx.x * blockDim.x + threadIdx.x;
    if (i < N) atomicAdd(&sc[bid[i]], 1);
    __syncthreads();
    if (threadIdx.x < NBATCH && sc[threadIdx.x] > 0)
        atomicAdd(&g_bcnt[threadIdx.x], (float)sc[threadIdx.x]);
}

// ---------------- W pack+transpose: Wb[t][n][k] = fp16(W[(t*256+k)*256 + n]) ----------------
__global__ void k_wpackT(const float* __restrict__ W, __half* __restrict__ Wb) {
    __shared__ float tile[32][33];
    int t = blockIdx.z;
    int k0 = blockIdx.x * 32, n0 = blockIdx.y * 32;
    for (int j = threadIdx.y; j < 32; j += 8)
        tile[j][threadIdx.x] = W[(size_t)(t * 256 + k0 + j) * C_DIM + n0 + threadIdx.x];
    __syncthreads();
    for (int j = threadIdx.y; j < 32; j += 8)
        Wb[((size_t)t * 256 + n0 + j) * C_DIM + k0 + threadIdx.x] =
            __float2half_rn(tile[threadIdx.x][j]);
}

// ---------------- GN ----------------
__global__ void k_gnstats(const float* __restrict__ src, const int* __restrict__ bid, int N) {
    __shared__ int sbid[NPB];
    int n0 = blockIdx.x * NPB;
    int nmax = min(N - n0, NPB);
    for (int i = threadIdx.x; i < nmax; i += blockDim.x) sbid[i] = bid[n0 + i];
    __syncthreads();
    int c = threadIdx.x;
    int g = c >> 3;
    float ls1 = 0.f, ls2 = 0.f;
    int cur = sbid[0];
    for (int i = 0; i < nmax; ++i) {
        int b = sbid[i];
        if (b != cur) {
            atomicAdd(&g_s1[cur * NGROUP + g], ls1);
            atomicAdd(&g_s2[cur * NGROUP + g], ls2);
            ls1 = 0.f; ls2 = 0.f; cur = b;
        }
        float v = src[(size_t)(n0 + i) * C_DIM + c];
        ls1 += v; ls2 += v * v;
    }
    atomicAdd(&g_s1[cur * NGROUP + g], ls1);
    atomicAdd(&g_s2[cur * NGROUP + g], ls2);
}
__global__ void k_gnfinal() {
    int i = threadIdx.x;
    int b = i >> 5;
    float n  = g_bcnt[b] * (float)CPG;
    float ic = 1.0f / (n + GN_EPS);
    float s1 = g_s1[i], s2 = g_s2[i];
    float m  = s1 * ic;
    float var = ic * (s2 - 2.f * m * s1 + m * m * n);
    g_mean[i] = m;
    g_istd[i] = rsqrtf(var + GN_EPS);
}
__global__ void k_gn_silu_h(const float* __restrict__ src, __half* __restrict__ dst,
                            const float* __restrict__ w, const float* __restrict__ bb,
                            const int* __restrict__ bid, int N) {
    int i = blockIdx.x * blockDim.x + threadIdx.x;
    int total = N * (C_DIM / 4);
    if (i >= total) return;
    int n  = i >> 6;
    int c4 = (i & 63) << 2;
    int b  = bid[n];
    int s  = b * NGROUP + (c4 >> 3);
    float m  = g_mean[s], is = g_istd[s];
    float4 xv = ((const float4*)src)[i];
    float4 wv = ((const float4*)w)[c4 >> 2];
    float4 bv = ((const float4*)bb)[c4 >> 2];
    float v0 = (xv.x - m) * is * wv.x + bv.x; v0 = v0 / (1.f + expf(-v0));
    float v1 = (xv.y - m) * is * wv.y + bv.y; v1 = v1 / (1.f + expf(-v1));
    float v2 = (xv.z - m) * is * wv.z + bv.z; v2 = v2 / (1.f + expf(-v2));
    float v3 = (xv.w - m) * is * wv.w + bv.w; v3 = v3 / (1.f + expf(-v3));
    __half2 h[2];
    h[0] = __floats2half2_rn(v0, v1);
    h[1] = __floats2half2_rn(v2, v3);
    *(uint2*)(dst + (size_t)n * C_DIM + c4) = *(uint2*)h;
}

// ---------------- CSR + needed-bitmap build ----------------
__global__ void k_ecount2(const int* __restrict__ erow, const int* __restrict__ ecol,
                          const int* __restrict__ et, int E, int N) {
    int e = blockIdx.x * blockDim.x + threadIdx.x;
    if (e < E) {
        int r = erow[e], t = et[e];
        atomicAdd(&g_cnt[r * NET + t], 1);
        atomicAdd(&g_rowcnt[r], 1);
        g_need[t * N + ecol[e]] = 1;     // idempotent plain store
    }
}
// row-degree scan (N elements)
__global__ void k_scan1(int N) {
    __shared__ int sh[256];
    int base = blockIdx.x * SCAN_B;
    int tid = threadIdx.x;
    int vals[8];
    int s = 0;
    #pragma unroll
    for (int j = 0; j < 8; ++j) {
        int idx = base + tid * 8 + j;
        int v = (idx < N) ? g_rowcnt[idx] : 0;
        vals[j] = s;
        s += v;
    }
    sh[tid] = s;
    __syncthreads();
    for (int off = 1; off < 256; off <<= 1) {
        int t = (tid >= off) ? sh[tid - off] : 0;
        __syncthreads();
        sh[tid] += t;
        __syncthreads();
    }
    int tb = tid ? sh[tid - 1] : 0;
    #pragma unroll
    for (int j = 0; j < 8; ++j) {
        int idx = base + tid * 8 + j;
        if (idx < N) g_offs[idx] = tb + vals[j];
    }
    if (tid == 255) g_blksum[blockIdx.x] = sh[255];
}
__global__ void k_scan2(int nb) {
    __shared__ int sh[64];
    int t = threadIdx.x;
    sh[t] = (t < nb) ? g_blksum[t] : 0;
    __syncthreads();
    for (int off = 1; off < 64; off <<= 1) {
        int v = (t >= off) ? sh[t - off] : 0;
        __syncthreads();
        sh[t] += v;
        __syncthreads();
    }
    if (t < nb) g_blksum[t] = t ? sh[t - 1] : 0;
}
__global__ void k_scan3(int N) {
    int i = blockIdx.x * blockDim.x + threadIdx.x;
    if (i < N) g_offs[i] += g_blksum[i / SCAN_B];
}
// indicator scan (7N elements) -> g_cpos
__global__ void k_scan1b(int M) {
    __shared__ int sh[256];
    int base = blockIdx.x * SCAN_B;
    int tid = threadIdx.x;
    int vals[8];
    int s = 0;
    #pragma unroll
    for (int j = 0; j < 8; ++j) {
        int idx = base + tid * 8 + j;
        int v = (idx < M && g_need[idx]) ? 1 : 0;
        vals[j] = s;
        s += v;
    }
    sh[tid] = s;
    __syncthreads();
    for (int off = 1; off < 256; off <<= 1) {
        int t = (tid >= off) ? sh[tid - off] : 0;
        __syncthreads();
        sh[tid] += t;
        __syncthreads();
    }
    int tb = tid ? sh[tid - 1] : 0;
    #pragma unroll
    for (int j = 0; j < 8; ++j) {
        int idx = base + tid * 8 + j;
        if (idx < M) g_cpos[idx] = tb + vals[j];
    }
    if (tid == 255) g_blksum2[blockIdx.x] = sh[255];
}
__global__ void k_scan2b(int nb) {
    __shared__ int sh[512];
    int t = threadIdx.x;
    sh[t] = (t < nb) ? g_blksum2[t] : 0;
    __syncthreads();
    for (int off = 1; off < 512; off <<= 1) {
        int v = (t >= off) ? sh[t - off] : 0;
        __syncthreads();
        sh[t] += v;
        __syncthreads();
    }
    if (t < nb) g_blksum2[t] = t ? sh[t - 1] : 0;
}
__global__ void k_scan3b(int M) {
    int i = blockIdx.x * blockDim.x + threadIdx.x;
    if (i < M) g_cpos[i] += g_blksum2[i / SCAN_B];
}
// type segment table (single thread)
__global__ void k_tseg(int N, int n7) {
    int tstart[8];
    for (int t = 0; t < NET; ++t) tstart[t] = g_cpos[t * N];
    tstart[7] = g_cpos[n7 - 1] + (g_need[n7 - 1] ? 1 : 0);
    int tp = 0;
    for (int t = 0; t < NET; ++t) {
        g_tstart[t] = tstart[t];
        g_tpadA[t] = tp;
        int cnt = tstart[t + 1] - tstart[t];
        tp += (cnt + 127) & ~127;
    }
    g_tstart[7] = tstart[7];
    g_tpadA[7] = tp;
    g_mtotal = tp;
}
__global__ void k_fillpos(int N, int n7) {
    int i = blockIdx.x * blockDim.x + threadIdx.x;
    if (i >= n7 || !g_need[i]) return;
    int t = i / N, c = i - t * N;
    int pos = g_tpadA[t] + g_cpos[i] - g_tstart[t];
    g_pos[i] = pos;
    g_clist[pos] = c;
}
__global__ void k_escatter(const int* __restrict__ erow, const int* __restrict__ ecol,
                           const int* __restrict__ et, int E, int N) {
    int e = blockIdx.x * blockDim.x + threadIdx.x;
    if (e >= E) return;
    int r = erow[e], t = et[e];
    int posIdx = g_offs[r] + atomicAdd(&g_cur[r], 1);
    int pos = g_pos[t * N + ecol[e]];
    g_eperm[posIdx] = (pos << 3) | t;
}

// ---------------- fp16 GEMM over compacted rows, cp.async 3-stage + ldmatrix ----------------
#define BM 128
#define BN 128
#define BK 32
#define KSTR 40
#define TILE_B (128 * KSTR * 2)
#define STAGE_B (2 * TILE_B)
#define NSTAGE 3
#define EPS_LD 136

__device__ __forceinline__ void mma_f16(float* d, const uint32_t* a, uint32_t b0, uint32_t b1) {
    asm volatile("mma.sync.aligned.m16n8k16.row.col.f32.f16.f16.f32 "
        "{%0,%1,%2,%3}, {%4,%5,%6,%7}, {%8,%9}, {%0,%1,%2,%3};\n"
        : "+f"(d[0]), "+f"(d[1]), "+f"(d[2]), "+f"(d[3])
        : "r"(a[0]), "r"(a[1]), "r"(a[2]), "r"(a[3]), "r"(b0), "r"(b1));
}
__device__ __forceinline__ void ldsm_x4(uint32_t* r, uint32_t addr) {
    asm volatile("ldmatrix.sync.aligned.m8n8.x4.shared.b16 {%0,%1,%2,%3}, [%4];\n"
        : "=r"(r[0]), "=r"(r[1]), "=r"(r[2]), "=r"(r[3]) : "r"(addr));
}

__global__ __launch_bounds__(256, 2)
void k_gemm_h(const __half* __restrict__ A, const __half* __restrict__ Wb,
              __half* __restrict__ Y) {
    int m0 = blockIdx.y * BM;
    if (m0 >= g_mtotal) return;

    __shared__ __align__(16) char sm[NSTAGE * STAGE_B];

    int tid  = threadIdx.x;
    int warp = tid >> 5, lane = tid & 31;
    int n0 = blockIdx.x * BN;               // 0 or 128 within the type block

    // resolve type from padded segment table
    int t = 0;
    #pragma unroll
    for (int q = 1; q < NET; ++q) t += (m0 >= g_tpadA[q]) ? 1 : 0;
    const __half* gB = Wb + ((size_t)t * 256 + n0) * C_DIM;

    int wm = warp >> 1, wn = warp & 1;
    int mBase = wm * 32, nBase = wn * 64;
    int grp = lane >> 2, tig = lane & 3;
    int mi = lane >> 3, lr = lane & 7;

    uint32_t sbase = (uint32_t)__cvta_generic_to_shared(sm);

    float acc[2][8][4];
    #pragma unroll
    for (int i = 0; i < 2; ++i)
        #pragma unroll
        for (int j = 0; j < 8; ++j)
            #pragma unroll
            for (int q = 0; q < 4; ++q) acc[i][j][q] = 0.f;

    int cRowA = tid >> 2, cQ = tid & 3;
    int cRowA2 = cRowA + 64;
    int col0 = g_clist[m0 + cRowA];
    int col1 = g_clist[m0 + cRowA2];

    auto issue = [&](int st, int kb) {
        uint32_t sa = sbase + st * STAGE_B;
        uint32_t sb = sa + TILE_B;
        {
            uint32_t d0 = sa + cRowA * (KSTR * 2) + cQ * 16;
            int z0 = (col0 >= 0) ? 16 : 0;
            const __half* p0 = z0 ? (A + (size_t)col0 * C_DIM + kb + cQ * 8) : A;
            asm volatile("cp.async.cg.shared.global [%0], [%1], 16, %2;\n"
                :: "r"(d0), "l"(p0), "r"(z0) : "memory");
            uint32_t d1 = sa + cRowA2 * (KSTR * 2) + cQ * 16;
            int z1 = (col1 >= 0) ? 16 : 0;
            const __half* p1 = z1 ? (A + (size_t)col1 * C_DIM + kb + cQ * 8) : A;
            asm volatile("cp.async.cg.shared.global [%0], [%1], 16, %2;\n"
                :: "r"(d1), "l"(p1), "r"(z1) : "memory");
        }
        {
            uint32_t d0 = sb + cRowA * (KSTR * 2) + cQ * 16;
            const __half* s0 = gB + (size_t)cRowA * C_DIM + kb + cQ * 8;
            asm volatile("cp.async.cg.shared.global [%0], [%1], 16, 16;\n"
                :: "r"(d0), "l"(s0) : "memory");
            uint32_t d1 = sb + cRowA2 * (KSTR * 2) + cQ * 16;
            const __half* s1 = gB + (size_t)cRowA2 * C_DIM + kb + cQ * 8;
            asm volatile("cp.async.cg.shared.global [%0], [%1], 16, 16;\n"
                :: "r"(d1), "l"(s1) : "memory");
        }
        asm volatile("cp.async.commit_group;\n" ::: "memory");
    };

    auto compute = [&](int st) {
        uint32_t sa = sbase + st * STAGE_B;
        uint32_t sb = sa + TILE_B;
        #pragma unroll
        for (int ks = 0; ks < 2; ++ks) {
            int k0 = ks * 16;
            uint32_t a[2][4];
            #pragma unroll
            for (int im = 0; im < 2; ++im) {
                int row = mBase + im * 16 + ((mi & 1) << 3) + lr;
                int col = k0 + ((mi >> 1) << 3);
                ldsm_x4(a[im], sa + (uint32_t)(row * KSTR + col) * 2);
            }
            #pragma unroll
            for (int nb = 0; nb < 4; ++nb) {
                uint32_t b[4];
                int row = nBase + nb * 16 + ((mi >> 1) << 3) + lr;
                int col = k0 + ((mi & 1) << 3);
                ldsm_x4(b, sb + (uint32_t)(row * KSTR + col) * 2);
                mma_f16(acc[0][nb * 2],     a[0], b[0], b[1]);
                mma_f16(acc[1][nb * 2],     a[1], b[0], b[1]);
                mma_f16(acc[0][nb * 2 + 1], a[0], b[2], b[3]);
                mma_f16(acc[1][nb * 2 + 1], a[1], b[2], b[3]);
            }
        }
    };

    issue(0, 0);
    issue(1, BK);
    #pragma unroll
    for (int it = 0; it < 8; ++it) {
        if (it + 2 < 8) {
            asm volatile("cp.async.wait_group 1;\n" ::: "memory");
        } else {
            asm volatile("cp.async.wait_group 0;\n" ::: "memory");
        }
        __syncthreads();
        if (it + 2 < 8) issue((it + 2) % 3, (it + 2) * BK);
        compute(it % 3);
    }

    // epilogue: stage via smem, coalesced uint4 stores to compacted Y [m][256]
    __syncthreads();
    __half* ep = (__half*)sm;
    #pragma unroll
    for (int im = 0; im < 2; ++im) {
        int r = mBase + im * 16 + grp;
        #pragma unroll
        for (int in = 0; in < 8; ++in) {
            int cc = nBase + in * 8 + tig * 2;
            *(__half2*)(ep + r * EPS_LD + cc) =
                __floats2half2_rn(acc[im][in][0], acc[im][in][1]);
            *(__half2*)(ep + (r + 8) * EPS_LD + cc) =
                __floats2half2_rn(acc[im][in][2], acc[im][in][3]);
        }
    }
    __syncthreads();
    #pragma unroll
    for (int j = 0; j < 8; ++j) {
        int idx = tid + j * 256;
        int row = idx >> 4, u = idx & 15;
        *(uint4*)(Y + (size_t)(m0 + row) * C_DIM + n0 + u * 8) =
            *(const uint4*)(ep + row * EPS_LD + u * 8);
    }
}

// ---------------- gather: one warp per row, compacted fp16 Y, zero atomics ----------------
__global__ void k_gather(const __half* __restrict__ Y, const float* __restrict__ resid,
                         float* __restrict__ out, int N, int addResid) {
    int w = (blockIdx.x * blockDim.x + threadIdx.x) >> 5;
    int lane = threadIdx.x & 31;
    if (w >= N) return;
    int beg = g_offs[w];
    int deg = g_rowcnt[w];
    const int* cntp = &g_cnt[w * NET];

    float acc[8] = {0.f, 0.f, 0.f, 0.f, 0.f, 0.f, 0.f, 0.f};

    for (int j = 0; j < deg; ++j) {
        int p = g_eperm[beg + j];
        int pos = p >> 3, t = p & 7;
        float inv = 1.f / (float)cntp[t];
        const uint4* src = (const uint4*)(Y + (size_t)pos * C_DIM) + lane;
        uint4 v = *src;
        const __half2* h = (const __half2*)&v;
        #pragma unroll
        for (int q = 0; q < 4; ++q) {
            float2 f = __half22float2(h[q]);
            acc[q * 2 + 0] += f.x * inv;
            acc[q * 2 + 1] += f.y * inv;
        }
    }

    float* orow = out + (size_t)w * C_DIM + lane * 8;
    if (addResid) {
        const float* rp = resid + (size_t)w * C_DIM + lane * 8;
        float4 r0 = *(const float4*)rp, r1 = *(const float4*)(rp + 4);
        acc[0] += r0.x; acc[1] += r0.y; acc[2] += r0.z; acc[3] += r0.w;
        acc[4] += r1.x; acc[5] += r1.y; acc[6] += r1.z; acc[7] += r1.w;
    }
    *(float4*)orow       = make_float4(acc[0], acc[1], acc[2], acc[3]);
    *(float4*)(orow + 4) = make_float4(acc[4], acc[5], acc[6], acc[7]);
}

// ---------------- launch ----------------
extern "C" void kernel_launch(void* const* d_in, const int* in_sizes, int n_in,
                              void* d_out, int out_size) {
    const float* x    = (const float*)d_in[0];
    const float* gn1w = (const float*)d_in[1];
    const float* gn1b = (const float*)d_in[2];
    const float* w1   = (const float*)d_in[3];
    const float* gn2w = (const float*)d_in[4];
    const float* gn2b = (const float*)d_in[5];
    const float* w2   = (const float*)d_in[6];
    const int*   eidx = (const int*)d_in[7];
    const int*   et   = (const int*)d_in[8];
    const int*   bid  = (const int*)d_in[9];

    int N = in_sizes[0] / C_DIM;
    int E = in_sizes[8];
    const int* erow = eidx;
    const int* ecol = eidx + E;

    float *p_acc;
    __half *p_h, *p_Y, *p_Wb1, *p_Wb2;
    cudaGetSymbolAddress((void**)&p_h,   g_h);
    cudaGetSymbolAddress((void**)&p_acc, g_acc);
    cudaGetSymbolAddress((void**)&p_Y,   g_Y);
    cudaGetSymbolAddress((void**)&p_Wb1, g_Wb1);
    cudaGetSymbolAddress((void**)&p_Wb2, g_Wb2);

    int n7 = N * NET;
    int t4 = N * (C_DIM / 4);
    int gnBlocks = (N + NPB - 1) / NPB;
    int nbScan  = (N + SCAN_B - 1) / SCAN_B;
    int nbScanB = (n7 + SCAN_B - 1) / SCAN_B;
    int maxYBlocks = (n7 + NET * 128 + BM - 1) / BM;   // padded-compaction upper bound
    dim3 gemmGrid(2, maxYBlocks);
    int gatherBlocks = (N + 7) / 8;
    dim3 wtGrid(8, 8, NET), wtBlock(32, 8);

    // --- init + W pack + compaction + CSR build ---
    k_init<<<(n7 + 1024 + 255) / 256, 256>>>(N, n7);
    k_wpackT<<<wtGrid, wtBlock>>>(w1, p_Wb1);
    k_wpackT<<<wtGrid, wtBlock>>>(w2, p_Wb2);
    k_bcount<<<(N + 255) / 256, 256>>>(bid, N);
    k_ecount2<<<(E + 255) / 256, 256>>>(erow, ecol, et, E, N);
    k_scan1<<<nbScan, 256>>>(N);
    k_scan2<<<1, 64>>>(nbScan);
    k_scan3<<<(N + 255) / 256, 256>>>(N);
    k_scan1b<<<nbScanB, 256>>>(n7);
    k_scan2b<<<1, 512>>>(nbScanB);
    k_scan3b<<<(n7 + 255) / 256, 256>>>(n7);
    k_tseg<<<1, 1>>>(N, n7);
    k_fillpos<<<(n7 + 255) / 256, 256>>>(N, n7);
    k_escatter<<<(E + 255) / 256, 256>>>(erow, ecol, et, E, N);

    // --- GN1 + silu (fp16 out) ---
    k_gnstats<<<gnBlocks, 256>>>(x, bid, N);
    k_gnfinal<<<1, 256>>>();
    k_gn_silu_h<<<(t4 + 255) / 256, 256>>>(x, p_h, gn1w, gn1b, bid, N);

    // --- conv1: compacted fp16 GEMM then CSR gather-mean ---
    k_gemm_h<<<gemmGrid, 256>>>(p_h, p_Wb1, p_Y);
    k_gather<<<gatherBlocks, 256>>>(p_Y, nullptr, p_acc, N, 0);

    // --- GN2 + silu (fp16 out) ---
    k_zero_stats<<<1, 256>>>();
    k_gnstats<<<gnBlocks, 256>>>(p_acc, bid, N);
    k_gnfinal<<<1, 256>>>();
    k_gn_silu_h<<<(t4 + 255) / 256, 256>>>(p_acc, p_h, gn2w, gn2b, bid, N);

    // --- conv2 + fused residual ---
    k_gemm_h<<<gemmGrid, 256>>>(p_h, p_Wb2, p_Y);
    k_gather<<<gatherBlocks, 256>>>(p_Y, x, (float*)d_out, N, 1);
}

// round 10
// speedup vs baseline: 3.3225x; 1.0644x over previous
#include <cuda_runtime.h>
#include <cuda_fp16.h>
#include <stdint.h>

#define C_DIM   256
#define NGROUP  32
#define CPG     8
#define NET     7
#define NBATCH  8
#define GN_EPS  1e-5f
#define MAXN    100000
#define MAXE    1048576
#define N7MAX   (MAXN * NET)
#define NPB     128
#define SCAN_B  2048

// ---------------- scratch ----------------
__device__ __half  g_h  [(size_t)MAXN * C_DIM];            // fp16 GEMM input
__device__ __half  g_acch[(size_t)MAXN * C_DIM];           // conv1 output (fp16)
__device__ __half  g_Y  [(size_t)(N7MAX + 1024) * C_DIM];  // compacted fp16 intermediate
__device__ __half  g_Wb1[NET * C_DIM * C_DIM];             // packed W1: [t][n][k] fp16
__device__ __half  g_Wb2[NET * C_DIM * C_DIM];
__device__ int     g_cnt[MAXN * NET];      // per (row, type) in-degree
__device__ int     g_rowcnt[MAXN];
__device__ int     g_offs[MAXN];
__device__ int     g_cur[MAXN];
__device__ int     g_blksum[64];
__device__ int     g_eperm[MAXE];          // (pos<<3) | type
// --- compaction state ---
__device__ int     g_need[N7MAX];
__device__ int     g_cpos[N7MAX];
__device__ int     g_blksum2[512];
__device__ int     g_pos [N7MAX];
__device__ int     g_clist[N7MAX + 1024];
__device__ int     g_tpadA[8];
__device__ int     g_tstart[8];
__device__ int     g_mtotal;
// --- GN state ---
__device__ float   g_s1 [NBATCH * NGROUP];
__device__ float   g_s2 [NBATCH * NGROUP];
__device__ float   g_mean[NBATCH * NGROUP];
__device__ float   g_istd[NBATCH * NGROUP];
__device__ float   g_bcnt[NBATCH];         // maintained zero-at-entry across launches

// ---------------- init (+ batch count fused) ----------------
__global__ void k_init(const int* __restrict__ bid, int N, int n7) {
    __shared__ int sc[NBATCH];
    if (threadIdx.x < NBATCH) sc[threadIdx.x] = 0;
    __syncthreads();
    int i = blockIdx.x * blockDim.x + threadIdx.x;
    if (i < n7) { g_cnt[i] = 0; g_need[i] = 0; }
    if (i < n7 + 1024) g_clist[i] = -1;
    if (i < N) { g_cur[i] = 0; atomicAdd(&sc[bid[i]], 1); }
    if (i < NBATCH * NGROUP) { g_s1[i] = 0.f; g_s2[i] = 0.f; }
    __syncthreads();
    if (threadIdx.x < NBATCH && sc[threadIdx.x] > 0)
        atomicAdd(&g_bcnt[threadIdx.x], (float)sc[threadIdx.x]);
}

// ---------------- W pack+transpose: Wb[t][n][k] = fp16(W[(t*256+k)*256 + n]) ----------------
__global__ void k_wpackT(const float* __restrict__ W, __half* __restrict__ Wb) {
    __shared__ float tile[32][33];
    int t = blockIdx.z;
    int k0 = blockIdx.x * 32, n0 = blockIdx.y * 32;
    for (int j = threadIdx.y; j < 32; j += 8)
        tile[j][threadIdx.x] = W[(size_t)(t * 256 + k0 + j) * C_DIM + n0 + threadIdx.x];
    __syncthreads();
    for (int j = threadIdx.y; j < 32; j += 8)
        Wb[((size_t)t * 256 + n0 + j) * C_DIM + k0 + threadIdx.x] =
            __float2half_rn(tile[threadIdx.x][j]);
}

// ---------------- GN ----------------
__global__ void k_gnstats(const float* __restrict__ src, const int* __restrict__ bid, int N) {
    __shared__ int sbid[NPB];
    int n0 = blockIdx.x * NPB;
    int nmax = min(N - n0, NPB);
    for (int i = threadIdx.x; i < nmax; i += blockDim.x) sbid[i] = bid[n0 + i];
    __syncthreads();
    int c = threadIdx.x;
    int g = c >> 3;
    float ls1 = 0.f, ls2 = 0.f;
    int cur = sbid[0];
    for (int i = 0; i < nmax; ++i) {
        int b = sbid[i];
        if (b != cur) {
            atomicAdd(&g_s1[cur * NGROUP + g], ls1);
            atomicAdd(&g_s2[cur * NGROUP + g], ls2);
            ls1 = 0.f; ls2 = 0.f; cur = b;
        }
        float v = src[(size_t)(n0 + i) * C_DIM + c];
        ls1 += v; ls2 += v * v;
    }
    atomicAdd(&g_s1[cur * NGROUP + g], ls1);
    atomicAdd(&g_s2[cur * NGROUP + g], ls2);
}
// reads s1/s2/bcnt, writes mean/istd, then zeroes s1/s2 (and bcnt when asked)
__global__ void k_gnfinal(int zero_bcnt) {
    int i = threadIdx.x;
    int b = i >> 5;
    float n  = g_bcnt[b] * (float)CPG;
    float ic = 1.0f / (n + GN_EPS);
    float s1 = g_s1[i], s2 = g_s2[i];
    float m  = s1 * ic;
    float var = ic * (s2 - 2.f * m * s1 + m * m * n);
    g_mean[i] = m;
    g_istd[i] = rsqrtf(var + GN_EPS);
    __syncthreads();
    g_s1[i] = 0.f; g_s2[i] = 0.f;
    if (zero_bcnt && i < NBATCH) g_bcnt[i] = 0.f;
}
// fp32 in -> fp16 out (GN1)
__global__ void k_gn_silu_h(const float* __restrict__ src, __half* __restrict__ dst,
                            const float* __restrict__ w, const float* __restrict__ bb,
                            const int* __restrict__ bid, int N) {
    int i = blockIdx.x * blockDim.x + threadIdx.x;
    int total = N * (C_DIM / 4);
    if (i >= total) return;
    int n  = i >> 6;
    int c4 = (i & 63) << 2;
    int b  = bid[n];
    int s  = b * NGROUP + (c4 >> 3);
    float m  = g_mean[s], is = g_istd[s];
    float4 xv = ((const float4*)src)[i];
    float4 wv = ((const float4*)w)[c4 >> 2];
    float4 bv = ((const float4*)bb)[c4 >> 2];
    float v0 = (xv.x - m) * is * wv.x + bv.x; v0 = v0 / (1.f + expf(-v0));
    float v1 = (xv.y - m) * is * wv.y + bv.y; v1 = v1 / (1.f + expf(-v1));
    float v2 = (xv.z - m) * is * wv.z + bv.z; v2 = v2 / (1.f + expf(-v2));
    float v3 = (xv.w - m) * is * wv.w + bv.w; v3 = v3 / (1.f + expf(-v3));
    __half2 h[2];
    h[0] = __floats2half2_rn(v0, v1);
    h[1] = __floats2half2_rn(v2, v3);
    *(uint2*)(dst + (size_t)n * C_DIM + c4) = *(uint2*)h;
}
// fp16 in -> fp16 out (GN2)
__global__ void k_gn_silu_hh(const __half* __restrict__ src, __half* __restrict__ dst,
                             const float* __restrict__ w, const float* __restrict__ bb,
                             const int* __restrict__ bid, int N) {
    int i = blockIdx.x * blockDim.x + threadIdx.x;
    int total = N * (C_DIM / 4);
    if (i >= total) return;
    int n  = i >> 6;
    int c4 = (i & 63) << 2;
    int b  = bid[n];
    int s  = b * NGROUP + (c4 >> 3);
    float m  = g_mean[s], is = g_istd[s];
    uint2 raw = *(const uint2*)(src + (size_t)n * C_DIM + c4);
    const __half2* hp = (const __half2*)&raw;
    float2 f0 = __half22float2(hp[0]);
    float2 f1 = __half22float2(hp[1]);
    float4 wv = ((const float4*)w)[c4 >> 2];
    float4 bv = ((const float4*)bb)[c4 >> 2];
    float v0 = (f0.x - m) * is * wv.x + bv.x; v0 = v0 / (1.f + expf(-v0));
    float v1 = (f0.y - m) * is * wv.y + bv.y; v1 = v1 / (1.f + expf(-v1));
    float v2 = (f1.x - m) * is * wv.z + bv.z; v2 = v2 / (1.f + expf(-v2));
    float v3 = (f1.y - m) * is * wv.w + bv.w; v3 = v3 / (1.f + expf(-v3));
    __half2 h[2];
    h[0] = __floats2half2_rn(v0, v1);
    h[1] = __floats2half2_rn(v2, v3);
    *(uint2*)(dst + (size_t)n * C_DIM + c4) = *(uint2*)h;
}

// ---------------- edge count + needed-bitmap ----------------
__global__ void k_ecount2(const int* __restrict__ erow, const int* __restrict__ ecol,
                          const int* __restrict__ et, int E, int N) {
    int e = blockIdx.x * blockDim.x + threadIdx.x;
    if (e < E) {
        int r = erow[e], t = et[e];
        atomicAdd(&g_cnt[r * NET + t], 1);
        g_need[t * N + ecol[e]] = 1;
    }
}
// row-degree scan; degrees derived from g_cnt row-sums
__global__ void k_scan1(int N) {
    __shared__ int sh[256];
    int base = blockIdx.x * SCAN_B;
    int tid = threadIdx.x;
    int vals[8];
    int s = 0;
    #pragma unroll
    for (int j = 0; j < 8; ++j) {
        int idx = base + tid * 8 + j;
        int v = 0;
        if (idx < N) {
            const int* cp = &g_cnt[idx * NET];
            #pragma unroll
            for (int q = 0; q < NET; ++q) v += cp[q];
            g_rowcnt[idx] = v;
        }
        vals[j] = s;
        s += v;
    }
    sh[tid] = s;
    __syncthreads();
    for (int off = 1; off < 256; off <<= 1) {
        int t = (tid >= off) ? sh[tid - off] : 0;
        __syncthreads();
        sh[tid] += t;
        __syncthreads();
    }
    int tb = tid ? sh[tid - 1] : 0;
    #pragma unroll
    for (int j = 0; j < 8; ++j) {
        int idx = base + tid * 8 + j;
        if (idx < N) g_offs[idx] = tb + vals[j];
    }
    if (tid == 255) g_blksum[blockIdx.x] = sh[255];
}
__global__ void k_scan2(int nb) {
    __shared__ int sh[64];
    int t = threadIdx.x;
    sh[t] = (t < nb) ? g_blksum[t] : 0;
    __syncthreads();
    for (int off = 1; off < 64; off <<= 1) {
        int v = (t >= off) ? sh[t - off] : 0;
        __syncthreads();
        sh[t] += v;
        __syncthreads();
    }
    if (t < nb) g_blksum[t] = t ? sh[t - 1] : 0;
}
__global__ void k_scan3(int N) {
    int i = blockIdx.x * blockDim.x + threadIdx.x;
    if (i < N) g_offs[i] += g_blksum[i / SCAN_B];
}
// indicator scan (7N)
__global__ void k_scan1b(int M) {
    __shared__ int sh[256];
    int base = blockIdx.x * SCAN_B;
    int tid = threadIdx.x;
    int vals[8];
    int s = 0;
    #pragma unroll
    for (int j = 0; j < 8; ++j) {
        int idx = base + tid * 8 + j;
        int v = (idx < M && g_need[idx]) ? 1 : 0;
        vals[j] = s;
        s += v;
    }
    sh[tid] = s;
    __syncthreads();
    for (int off = 1; off < 256; off <<= 1) {
        int t = (tid >= off) ? sh[tid - off] : 0;
        __syncthreads();
        sh[tid] += t;
        __syncthreads();
    }
    int tb = tid ? sh[tid - 1] : 0;
    #pragma unroll
    for (int j = 0; j < 8; ++j) {
        int idx = base + tid * 8 + j;
        if (idx < M) g_cpos[idx] = tb + vals[j];
    }
    if (tid == 255) g_blksum2[blockIdx.x] = sh[255];
}
// block-sum scan + type segment table (fused)
__global__ void k_scan2b(int nb, int N, int n7) {
    __shared__ int sh[512];
    int t = threadIdx.x;
    sh[t] = (t < nb) ? g_blksum2[t] : 0;
    __syncthreads();
    for (int off = 1; off < 512; off <<= 1) {
        int v = (t >= off) ? sh[t - off] : 0;
        __syncthreads();
        sh[t] += v;
        __syncthreads();
    }
    if (t < nb) g_blksum2[t] = t ? sh[t - 1] : 0;
    __syncthreads();
    if (t == 0) {
        int tstart[8];
        for (int q = 0; q < NET; ++q) {
            int idx = q * N;
            tstart[q] = g_cpos[idx] + g_blksum2[idx / SCAN_B];
        }
        int last = n7 - 1;
        tstart[7] = g_cpos[last] + g_blksum2[last / SCAN_B] + (g_need[last] ? 1 : 0);
        int tp = 0;
        for (int q = 0; q < NET; ++q) {
            g_tstart[q] = tstart[q];
            g_tpadA[q] = tp;
            tp += (tstart[q + 1] - tstart[q] + 127) & ~127;
        }
        g_tstart[7] = tstart[7];
        g_tpadA[7] = tp;
        g_mtotal = tp;
    }
}
__global__ void k_scan3b(int M) {
    int i = blockIdx.x * blockDim.x + threadIdx.x;
    if (i < M) g_cpos[i] += g_blksum2[i / SCAN_B];
}
__global__ void k_fillpos(int N, int n7) {
    int i = blockIdx.x * blockDim.x + threadIdx.x;
    if (i >= n7 || !g_need[i]) return;
    int t = i / N, c = i - t * N;
    int pos = g_tpadA[t] + g_cpos[i] - g_tstart[t];
    g_pos[i] = pos;
    g_clist[pos] = c;
}
__global__ void k_escatter(const int* __restrict__ erow, const int* __restrict__ ecol,
                           const int* __restrict__ et, int E, int N) {
    int e = blockIdx.x * blockDim.x + threadIdx.x;
    if (e >= E) return;
    int r = erow[e], t = et[e];
    int posIdx = g_offs[r] + atomicAdd(&g_cur[r], 1);
    int pos = g_pos[t * N + ecol[e]];
    g_eperm[posIdx] = (pos << 3) | t;
}

// ---------------- fp16 GEMM over compacted rows, cp.async 3-stage + ldmatrix ----------------
#define BM 128
#define BN 128
#define BK 32
#define KSTR 40
#define TILE_B (128 * KSTR * 2)
#define STAGE_B (2 * TILE_B)
#define NSTAGE 3
#define EPS_LD 136

__device__ __forceinline__ void mma_f16(float* d, const uint32_t* a, uint32_t b0, uint32_t b1) {
    asm volatile("mma.sync.aligned.m16n8k16.row.col.f32.f16.f16.f32 "
        "{%0,%1,%2,%3}, {%4,%5,%6,%7}, {%8,%9}, {%0,%1,%2,%3};\n"
        : "+f"(d[0]), "+f"(d[1]), "+f"(d[2]), "+f"(d[3])
        : "r"(a[0]), "r"(a[1]), "r"(a[2]), "r"(a[3]), "r"(b0), "r"(b1));
}
__device__ __forceinline__ void ldsm_x4(uint32_t* r, uint32_t addr) {
    asm volatile("ldmatrix.sync.aligned.m8n8.x4.shared.b16 {%0,%1,%2,%3}, [%4];\n"
        : "=r"(r[0]), "=r"(r[1]), "=r"(r[2]), "=r"(r[3]) : "r"(addr));
}

__global__ __launch_bounds__(256, 2)
void k_gemm_h(const __half* __restrict__ A, const __half* __restrict__ Wb,
              __half* __restrict__ Y) {
    int m0 = blockIdx.y * BM;
    if (m0 >= g_mtotal) return;

    __shared__ __align__(16) char sm[NSTAGE * STAGE_B];

    int tid  = threadIdx.x;
    int warp = tid >> 5, lane = tid & 31;
    int n0 = blockIdx.x * BN;

    int t = 0;
    #pragma unroll
    for (int q = 1; q < NET; ++q) t += (m0 >= g_tpadA[q]) ? 1 : 0;
    const __half* gB = Wb + ((size_t)t * 256 + n0) * C_DIM;

    int wm = warp >> 1, wn = warp & 1;
    int mBase = wm * 32, nBase = wn * 64;
    int grp = lane >> 2, tig = lane & 3;
    int mi = lane >> 3, lr = lane & 7;

    uint32_t sbase = (uint32_t)__cvta_generic_to_shared(sm);

    float acc[2][8][4];
    #pragma unroll
    for (int i = 0; i < 2; ++i)
        #pragma unroll
        for (int j = 0; j < 8; ++j)
            #pragma unroll
            for (int q = 0; q < 4; ++q) acc[i][j][q] = 0.f;

    int cRowA = tid >> 2, cQ = tid & 3;
    int cRowA2 = cRowA + 64;
    int col0 = g_clist[m0 + cRowA];
    int col1 = g_clist[m0 + cRowA2];

    auto issue = [&](int st, int kb) {
        uint32_t sa = sbase + st * STAGE_B;
        uint32_t sb = sa + TILE_B;
        {
            uint32_t d0 = sa + cRowA * (KSTR * 2) + cQ * 16;
            int z0 = (col0 >= 0) ? 16 : 0;
            const __half* p0 = z0 ? (A + (size_t)col0 * C_DIM + kb + cQ * 8) : A;
            asm volatile("cp.async.cg.shared.global [%0], [%1], 16, %2;\n"
                :: "r"(d0), "l"(p0), "r"(z0) : "memory");
            uint32_t d1 = sa + cRowA2 * (KSTR * 2) + cQ * 16;
            int z1 = (col1 >= 0) ? 16 : 0;
            const __half* p1 = z1 ? (A + (size_t)col1 * C_DIM + kb + cQ * 8) : A;
            asm volatile("cp.async.cg.shared.global [%0], [%1], 16, %2;\n"
                :: "r"(d1), "l"(p1), "r"(z1) : "memory");
        }
        {
            uint32_t d0 = sb + cRowA * (KSTR * 2) + cQ * 16;
            const __half* s0 = gB + (size_t)cRowA * C_DIM + kb + cQ * 8;
            asm volatile("cp.async.cg.shared.global [%0], [%1], 16, 16;\n"
                :: "r"(d0), "l"(s0) : "memory");
            uint32_t d1 = sb + cRowA2 * (KSTR * 2) + cQ * 16;
            const __half* s1 = gB + (size_t)cRowA2 * C_DIM + kb + cQ * 8;
            asm volatile("cp.async.cg.shared.global [%0], [%1], 16, 16;\n"
                :: "r"(d1), "l"(s1) : "memory");
        }
        asm volatile("cp.async.commit_group;\n" ::: "memory");
    };

    auto compute = [&](int st) {
        uint32_t sa = sbase + st * STAGE_B;
        uint32_t sb = sa + TILE_B;
        #pragma unroll
        for (int ks = 0; ks < 2; ++ks) {
            int k0 = ks * 16;
            uint32_t a[2][4];
            #pragma unroll
            for (int im = 0; im < 2; ++im) {
                int row = mBase + im * 16 + ((mi & 1) << 3) + lr;
                int col = k0 + ((mi >> 1) << 3);
                ldsm_x4(a[im], sa + (uint32_t)(row * KSTR + col) * 2);
            }
            #pragma unroll
            for (int nb = 0; nb < 4; ++nb) {
                uint32_t b[4];
                int row = nBase + nb * 16 + ((mi >> 1) << 3) + lr;
                int col = k0 + ((mi & 1) << 3);
                ldsm_x4(b, sb + (uint32_t)(row * KSTR + col) * 2);
                mma_f16(acc[0][nb * 2],     a[0], b[0], b[1]);
                mma_f16(acc[1][nb * 2],     a[1], b[0], b[1]);
                mma_f16(acc[0][nb * 2 + 1], a[0], b[2], b[3]);
                mma_f16(acc[1][nb * 2 + 1], a[1], b[2], b[3]);
            }
        }
    };

    issue(0, 0);
    issue(1, BK);
    #pragma unroll
    for (int it = 0; it < 8; ++it) {
        if (it + 2 < 8) {
            asm volatile("cp.async.wait_group 1;\n" ::: "memory");
        } else {
            asm volatile("cp.async.wait_group 0;\n" ::: "memory");
        }
        __syncthreads();
        if (it + 2 < 8) issue((it + 2) % 3, (it + 2) * BK);
        compute(it % 3);
    }

    __syncthreads();
    __half* ep = (__half*)sm;
    #pragma unroll
    for (int im = 0; im < 2; ++im) {
        int r = mBase + im * 16 + grp;
        #pragma unroll
        for (int in = 0; in < 8; ++in) {
            int cc = nBase + in * 8 + tig * 2;
            *(__half2*)(ep + r * EPS_LD + cc) =
                __floats2half2_rn(acc[im][in][0], acc[im][in][1]);
            *(__half2*)(ep + (r + 8) * EPS_LD + cc) =
                __floats2half2_rn(acc[im][in][2], acc[im][in][3]);
        }
    }
    __syncthreads();
    #pragma unroll
    for (int j = 0; j < 8; ++j) {
        int idx = tid + j * 256;
        int row = idx >> 4, u = idx & 15;
        *(uint4*)(Y + (size_t)(m0 + row) * C_DIM + n0 + u * 8) =
            *(const uint4*)(ep + row * EPS_LD + u * 8);
    }
}

// ---------------- conv1 gather: fp16 out + fused GN2 stats (lane == group) ----------------
__global__ void k_gather_gn(const __half* __restrict__ Y, __half* __restrict__ outh,
                            const int* __restrict__ bid, int N) {
    __shared__ float sh1[NBATCH * NGROUP], sh2[NBATCH * NGROUP];
    int tid = threadIdx.x;
    sh1[tid] = 0.f; sh2[tid] = 0.f;
    __syncthreads();

    int w = (blockIdx.x * blockDim.x + tid) >> 5;
    int lane = tid & 31;
    if (w < N) {
        int beg = g_offs[w];
        int deg = g_rowcnt[w];
        const int* cntp = &g_cnt[w * NET];
        float acc[8] = {0.f, 0.f, 0.f, 0.f, 0.f, 0.f, 0.f, 0.f};
        for (int j = 0; j < deg; ++j) {
            int p = g_eperm[beg + j];
            int pos = p >> 3, t = p & 7;
            float inv = 1.f / (float)cntp[t];
            uint4 v = *((const uint4*)(Y + (size_t)pos * C_DIM) + lane);
            const __half2* h = (const __half2*)&v;
            #pragma unroll
            for (int q = 0; q < 4; ++q) {
                float2 f = __half22float2(h[q]);
                acc[q * 2 + 0] += f.x * inv;
                acc[q * 2 + 1] += f.y * inv;
            }
        }
        __half2 ho[4];
        #pragma unroll
        for (int q = 0; q < 4; ++q)
            ho[q] = __floats2half2_rn(acc[q * 2], acc[q * 2 + 1]);
        *(uint4*)(outh + (size_t)w * C_DIM + lane * 8) = *(uint4*)ho;

        float ls1 = 0.f, ls2 = 0.f;
        #pragma unroll
        for (int q = 0; q < 8; ++q) { ls1 += acc[q]; ls2 += acc[q] * acc[q]; }
        int b = bid[w];
        atomicAdd(&sh1[b * NGROUP + lane], ls1);
        atomicAdd(&sh2[b * NGROUP + lane], ls2);
    }
    __syncthreads();
    float v1 = sh1[tid], v2 = sh2[tid];
    if (v1 != 0.f) atomicAdd(&g_s1[tid], v1);
    if (v2 != 0.f) atomicAdd(&g_s2[tid], v2);
}

// ---------------- conv2 gather: fp32 out + residual ----------------
__global__ void k_gather(const __half* __restrict__ Y, const float* __restrict__ resid,
                         float* __restrict__ out, int N) {
    int w = (blockIdx.x * blockDim.x + threadIdx.x) >> 5;
    int lane = threadIdx.x & 31;
    if (w >= N) return;
    int beg = g_offs[w];
    int deg = g_rowcnt[w];
    const int* cntp = &g_cnt[w * NET];

    float acc[8] = {0.f, 0.f, 0.f, 0.f, 0.f, 0.f, 0.f, 0.f};
    for (int j = 0; j < deg; ++j) {
        int p = g_eperm[beg + j];
        int pos = p >> 3, t = p & 7;
        float inv = 1.f / (float)cntp[t];
        uint4 v = *((const uint4*)(Y + (size_t)pos * C_DIM) + lane);
        const __half2* h = (const __half2*)&v;
        #pragma unroll
        for (int q = 0; q < 4; ++q) {
            float2 f = __half22float2(h[q]);
            acc[q * 2 + 0] += f.x * inv;
            acc[q * 2 + 1] += f.y * inv;
        }
    }
    const float* rp = resid + (size_t)w * C_DIM + lane * 8;
    float4 r0 = *(const float4*)rp, r1 = *(const float4*)(rp + 4);
    acc[0] += r0.x; acc[1] += r0.y; acc[2] += r0.z; acc[3] += r0.w;
    acc[4] += r1.x; acc[5] += r1.y; acc[6] += r1.z; acc[7] += r1.w;
    float* orow = out + (size_t)w * C_DIM + lane * 8;
    *(float4*)orow       = make_float4(acc[0], acc[1], acc[2], acc[3]);
    *(float4*)(orow + 4) = make_float4(acc[4], acc[5], acc[6], acc[7]);
}

// ---------------- launch ----------------
extern "C" void kernel_launch(void* const* d_in, const int* in_sizes, int n_in,
                              void* d_out, int out_size) {
    const float* x    = (const float*)d_in[0];
    const float* gn1w = (const float*)d_in[1];
    const float* gn1b = (const float*)d_in[2];
    const float* w1   = (const float*)d_in[3];
    const float* gn2w = (const float*)d_in[4];
    const float* gn2b = (const float*)d_in[5];
    const float* w2   = (const float*)d_in[6];
    const int*   eidx = (const int*)d_in[7];
    const int*   et   = (const int*)d_in[8];
    const int*   bid  = (const int*)d_in[9];

    int N = in_sizes[0] / C_DIM;
    int E = in_sizes[8];
    const int* erow = eidx;
    const int* ecol = eidx + E;

    __half *p_h, *p_acch, *p_Y, *p_Wb1, *p_Wb2;
    cudaGetSymbolAddress((void**)&p_h,    g_h);
    cudaGetSymbolAddress((void**)&p_acch, g_acch);
    cudaGetSymbolAddress((void**)&p_Y,    g_Y);
    cudaGetSymbolAddress((void**)&p_Wb1,  g_Wb1);
    cudaGetSymbolAddress((void**)&p_Wb2,  g_Wb2);

    int n7 = N * NET;
    int t4 = N * (C_DIM / 4);
    int gnBlocks = (N + NPB - 1) / NPB;
    int nbScan  = (N + SCAN_B - 1) / SCAN_B;
    int nbScanB = (n7 + SCAN_B - 1) / SCAN_B;
    int maxYBlocks = (n7 + NET * 128 + BM - 1) / BM;
    dim3 gemmGrid(2, maxYBlocks);
    int gatherBlocks = (N + 7) / 8;
    dim3 wtGrid(8, 8, NET), wtBlock(32, 8);

    // --- init (+bcount) + W pack + compaction + CSR build ---
    k_init<<<(n7 + 1024 + 255) / 256, 256>>>(bid, N, n7);
    k_wpackT<<<wtGrid, wtBlock>>>(w1, p_Wb1);
    k_wpackT<<<wtGrid, wtBlock>>>(w2, p_Wb2);
    k_ecount2<<<(E + 255) / 256, 256>>>(erow, ecol, et, E, N);
    k_scan1<<<nbScan, 256>>>(N);
    k_scan2<<<1, 64>>>(nbScan);
    k_scan3<<<(N + 255) / 256, 256>>>(N);
    k_scan1b<<<nbScanB, 256>>>(n7);
    k_scan2b<<<1, 512>>>(nbScanB, N, n7);
    k_scan3b<<<(n7 + 255) / 256, 256>>>(n7);
    k_fillpos<<<(n7 + 255) / 256, 256>>>(N, n7);
    k_escatter<<<(E + 255) / 256, 256>>>(erow, ecol, et, E, N);

    // --- GN1 + silu (fp16 out) ---
    k_gnstats<<<gnBlocks, 256>>>(x, bid, N);
    k_gnfinal<<<1, 256>>>(0);
    k_gn_silu_h<<<(t4 + 255) / 256, 256>>>(x, p_h, gn1w, gn1b, bid, N);

    // --- conv1: compacted fp16 GEMM, then gather + fused GN2 stats ---
    k_gemm_h<<<gemmGrid, 256>>>(p_h, p_Wb1, p_Y);
    k_gather_gn<<<gatherBlocks, 256>>>(p_Y, p_acch, bid, N);

    // --- GN2 + silu (fp16 in/out) ---
    k_gnfinal<<<1, 256>>>(1);
    k_gn_silu_hh<<<(t4 + 255) / 256, 256>>>(p_acch, p_h, gn2w, gn2b, bid, N);

    // --- conv2 + fused residual ---
    k_gemm_h<<<gemmGrid, 256>>>(p_h, p_Wb2, p_Y);
    k_gather<<<gatherBlocks, 256>>>(p_Y, x, (float*)d_out, N);
}